// round 3
// baseline (speedup 1.0000x reference)
#include <cuda_runtime.h>
#include <math_constants.h>

#define DM   1024
#define HS   64
#define BB   4
#define TT   2048
#define ROWS (BB * TT)        /* 8192 */
#define NS   16               /* key splits (SPLIT = q-tile = 128) */
#define SPLIT 128
#define KTILE 16
#define TRI  136              /* 16*17/2 active (qt,ks) pairs per batch */

typedef unsigned long long u64;

/* ---------------- f32x2 packed math helpers ---------------------------- */
__device__ __forceinline__ void fma2(u64& d, u64 a, u64 b) {
    asm("fma.rn.f32x2 %0, %1, %2, %3;" : "=l"(d) : "l"(a), "l"(b), "l"(d));
}
__device__ __forceinline__ void mul2(u64& d, u64 a, u64 b) {
    asm("mul.rn.f32x2 %0, %1, %2;" : "=l"(d) : "l"(a), "l"(b));
}
__device__ __forceinline__ void add2(u64& d, u64 a, u64 b) {
    asm("add.rn.f32x2 %0, %1, %2;" : "=l"(d) : "l"(a), "l"(b));
}
__device__ __forceinline__ u64 dup2(float x) {
    u64 r;
    unsigned u = __float_as_uint(x);
    asm("mov.b64 %0, {%1, %1};" : "=l"(r) : "r"(u));
    return r;
}
__device__ __forceinline__ float2 unpk(u64 v) {
    unsigned lo, hi;
    asm("mov.b64 {%0, %1}, %2;" : "=r"(lo), "=r"(hi) : "l"(v));
    return make_float2(__uint_as_float(lo), __uint_as_float(hi));
}

/* ---------------- device scratch ---------------------------------------- */
__device__ float g_q[ROWS * HS];
__device__ float g_k[ROWS * HS];
__device__ float g_v[ROWS * HS];
__device__ float g_po[(size_t)NS * ROWS * HS];
__device__ float g_pm[NS * ROWS];
__device__ float g_pl[NS * ROWS];

/* ---------------- fused QKV projection (f32x2, zero inner-loop MOVs) ----
 * 64x64 tile, 256 threads, 4 rows x 4 cols per thread.
 * A staged DUPLICATED+transposed in smem ({a,a} u64 pairs); B staged plain so
 * column pairs load directly as u64. Inner loop: 3 LDS.128 + 8 FFMA2. */
__global__ __launch_bounds__(256)
void qkv_kernel(const float* __restrict__ x,
                const float* __restrict__ Wq, const float* __restrict__ bq,
                const float* __restrict__ Wk, const float* __restrict__ bk,
                const float* __restrict__ Wv) {
    __shared__ float Asd[32][132];   /* [k][2*row + {0,1}] duplicated */
    __shared__ float Bs[32][64];     /* [k][col] */

    const int which = blockIdx.y;
    const float* __restrict__ W = (which == 0) ? Wq : ((which == 1) ? Wk : Wv);
    float* __restrict__ out = (which == 0) ? g_q : ((which == 1) ? g_k : g_v);

    const int row0 = blockIdx.x * 64;
    const int tid  = threadIdx.x;
    const int tx   = tid & 15;      /* 16 col groups x 4 cols */
    const int ty   = tid >> 4;      /* 16 row groups x 4 rows */

    /* loaders: A 64x32 (2 float4/thread), B 32x64 (2 float4/thread) */
    const int arow = tid & 63;
    const int ac   = (tid >> 6) * 8;
    const int brow = tid >> 3;
    const int bc   = (tid & 7) * 8;

    const float* xA = x + (size_t)(row0 + arow) * DM + ac;
    const float* wB = W + (size_t)brow * HS + bc;

    float4 pa[2], pb[2];
    pa[0] = *(const float4*)(xA);     pa[1] = *(const float4*)(xA + 4);
    pb[0] = *(const float4*)(wB);     pb[1] = *(const float4*)(wB + 4);

    u64 acc[4][2];
    #pragma unroll
    for (int i = 0; i < 4; i++) { acc[i][0] = 0ull; acc[i][1] = 0ull; }

    for (int k0 = 0; k0 < DM; k0 += 32) {
        #pragma unroll
        for (int i = 0; i < 2; i++) {
            float4 va = pa[i];
            *(u64*)&Asd[ac + i * 4 + 0][2 * arow] = dup2(va.x);
            *(u64*)&Asd[ac + i * 4 + 1][2 * arow] = dup2(va.y);
            *(u64*)&Asd[ac + i * 4 + 2][2 * arow] = dup2(va.z);
            *(u64*)&Asd[ac + i * 4 + 3][2 * arow] = dup2(va.w);
            *(float4*)&Bs[brow][bc + i * 4] = pb[i];
        }
        __syncthreads();

        if (k0 + 32 < DM) {
            xA += 32;
            wB += (size_t)32 * HS;
            pa[0] = *(const float4*)(xA);  pa[1] = *(const float4*)(xA + 4);
            pb[0] = *(const float4*)(wB);  pb[1] = *(const float4*)(wB + 4);
        }

        #pragma unroll
        for (int k = 0; k < 32; k++) {
            ulonglong2 a01 = *(const ulonglong2*)&Asd[k][8 * ty];       /* rows 4ty,4ty+1 dup'd */
            ulonglong2 a23 = *(const ulonglong2*)&Asd[k][8 * ty + 4];   /* rows 4ty+2,4ty+3 */
            ulonglong2 bb  = *(const ulonglong2*)&Bs[k][4 * tx];        /* col pairs */
            fma2(acc[0][0], a01.x, bb.x); fma2(acc[0][1], a01.x, bb.y);
            fma2(acc[1][0], a01.y, bb.x); fma2(acc[1][1], a01.y, bb.y);
            fma2(acc[2][0], a23.x, bb.x); fma2(acc[2][1], a23.x, bb.y);
            fma2(acc[3][0], a23.y, bb.x); fma2(acc[3][1], a23.y, bb.y);
        }
        __syncthreads();
    }

    float4 bias = make_float4(0.f, 0.f, 0.f, 0.f);
    if (which == 0)      bias = *(const float4*)&bq[tx * 4];
    else if (which == 1) bias = *(const float4*)&bk[tx * 4];

    #pragma unroll
    for (int r = 0; r < 4; r++) {
        float2 c0 = unpk(acc[r][0]);
        float2 c1 = unpk(acc[r][1]);
        float4 v;
        v.x = c0.x + bias.x; v.y = c0.y + bias.y;
        v.z = c1.x + bias.z; v.w = c1.y + bias.w;
        *(float4*)&out[(size_t)(row0 + ty * 4 + r) * HS + tx * 4] = v;
    }
}

/* ---------------- causal flash-attention (2 threads per query row) ------ */
__global__ __launch_bounds__(256)
void attn_split_kernel() {
    /* triangle index -> (qt, ks), ks <= qt; every block does 128 keys */
    int t = blockIdx.x;
    int b = blockIdx.y;
    int qt = (int)((sqrtf(8.f * (float)t + 1.f) - 1.f) * 0.5f);
    while ((qt + 1) * (qt + 2) / 2 <= t) qt++;
    while (qt * (qt + 1) / 2 > t) qt--;
    int ks = t - qt * (qt + 1) / 2;

    const int tid = threadIdx.x;
    const int h   = tid & 1;             /* dim half: 0 -> [0,32), 1 -> [32,64) */
    const int r   = qt * SPLIT + (tid >> 1);
    const int grow = b * TT + r;

    __shared__ float4 Ks[KTILE * 16];
    __shared__ float4 Vs[KTILE * 16];

    u64 q2[16];
    {
        const ulonglong2* qp = (const ulonglong2*)(g_q + (size_t)grow * HS + h * 32);
        #pragma unroll
        for (int i = 0; i < 8; i++) {
            ulonglong2 v = qp[i];
            q2[2 * i] = v.x; q2[2 * i + 1] = v.y;
        }
    }

    u64 o2[16];
    #pragma unroll
    for (int i = 0; i < 16; i++) o2[i] = 0ull;
    float m = -CUDART_INF_F;
    float l = 0.f;

    const int rmaxw = r | 15;            /* warp covers 16 consecutive rows */

    for (int tile = 0; tile < SPLIT / KTILE; tile++) {
        const int j0 = ks * SPLIT + tile * KTILE;
        __syncthreads();
        {
            const float4* kp = (const float4*)(g_k + (size_t)(b * TT + j0) * HS);
            const float4* vp = (const float4*)(g_v + (size_t)(b * TT + j0) * HS);
            Ks[tid] = kp[tid];
            Vs[tid] = vp[tid];
        }
        __syncthreads();

        if (j0 <= rmaxw) {               /* warp-uniform: skip fully-masked tiles */
            const int jr = r - j0;
            float sc[KTILE];
            float tmax = -CUDART_INF_F;
            #pragma unroll
            for (int j = 0; j < KTILE; j++) {
                const ulonglong2* kk = (const ulonglong2*)&Ks[j * 16 + h * 8];
                u64 a0 = 0ull, a1 = 0ull, a2 = 0ull, a3 = 0ull;
                #pragma unroll
                for (int d = 0; d < 8; d += 2) {
                    ulonglong2 kv0 = kk[d];
                    fma2(a0, q2[2 * d + 0], kv0.x);
                    fma2(a1, q2[2 * d + 1], kv0.y);
                    ulonglong2 kv1 = kk[d + 1];
                    fma2(a2, q2[2 * d + 2], kv1.x);
                    fma2(a3, q2[2 * d + 3], kv1.y);
                }
                add2(a0, a0, a2);
                add2(a1, a1, a3);
                float2 u = unpk(a0);
                float2 w = unpk(a1);
                float sh = (u.x + u.y) + (w.x + w.y);
                float s  = (sh + __shfl_xor_sync(0xffffffffu, sh, 1)) * 8.0f;
                sc[j] = (j <= jr) ? s : -CUDART_INF_F;
                tmax = fmaxf(tmax, sc[j]);
            }

            float mnew = fmaxf(m, tmax);
            float scale = __expf(m - mnew);      /* m=-inf -> 0, safe */
            m = mnew;
            l *= scale;
            u64 sd = dup2(scale);
            #pragma unroll
            for (int i = 0; i < 16; i++) mul2(o2[i], o2[i], sd);

            #pragma unroll
            for (int j = 0; j < KTILE; j++) {
                float p = __expf(sc[j] - mnew);
                l += p;
                u64 pd = dup2(p);
                const ulonglong2* vv = (const ulonglong2*)&Vs[j * 16 + h * 8];
                #pragma unroll
                for (int d = 0; d < 8; d++) {
                    ulonglong2 w = vv[d];
                    fma2(o2[2 * d + 0], pd, w.x);
                    fma2(o2[2 * d + 1], pd, w.y);
                }
            }
        }
    }

    if (h == 0) {
        g_pm[ks * ROWS + grow] = m;
        g_pl[ks * ROWS + grow] = l;
    }
    ulonglong2* po = (ulonglong2*)(g_po + ((size_t)ks * ROWS + grow) * HS + h * 32);
    #pragma unroll
    for (int i = 0; i < 8; i++) {
        ulonglong2 v; v.x = o2[2 * i]; v.y = o2[2 * i + 1];
        po[i] = v;
    }
}

/* ---------------- combine split partials -------------------------------- */
__global__ __launch_bounds__(256)
void attn_combine_kernel(float* __restrict__ out) {
    int t = blockIdx.x * blockDim.x + threadIdx.x;   /* (row, d4) */
    if (t >= ROWS * 16) return;
    int row = t >> 4;
    int d4  = t & 15;
    int smax = (row & (TT - 1)) >> 7;   /* active splits: 0..smax */

    float m = -CUDART_INF_F;
    for (int s = 0; s <= smax; s++) m = fmaxf(m, g_pm[s * ROWS + row]);

    float l = 0.f;
    float4 acc = make_float4(0.f, 0.f, 0.f, 0.f);
    for (int s = 0; s <= smax; s++) {
        float w = __expf(g_pm[s * ROWS + row] - m);
        l += g_pl[s * ROWS + row] * w;
        float4 p = ((const float4*)g_po)[((size_t)s * ROWS + row) * 16 + d4];
        acc.x = fmaf(w, p.x, acc.x);
        acc.y = fmaf(w, p.y, acc.y);
        acc.z = fmaf(w, p.z, acc.z);
        acc.w = fmaf(w, p.w, acc.w);
    }
    float inv = 1.f / l;
    ((float4*)out)[(size_t)row * 16 + d4] =
        make_float4(acc.x * inv, acc.y * inv, acc.z * inv, acc.w * inv);
}

/* ---------------- launch ------------------------------------------------ */
extern "C" void kernel_launch(void* const* d_in, const int* in_sizes, int n_in,
                              void* d_out, int out_size) {
    (void)in_sizes; (void)n_in; (void)out_size;
    const float* x  = (const float*)d_in[0];
    const float* Wq = (const float*)d_in[1];
    const float* bq = (const float*)d_in[2];
    const float* Wk = (const float*)d_in[3];
    const float* bk = (const float*)d_in[4];
    const float* Wv = (const float*)d_in[5];

    qkv_kernel<<<dim3(ROWS / 64, 3), 256>>>(x, Wq, bq, Wk, bk, Wv);
    attn_split_kernel<<<dim3(TRI, BB), 256>>>();
    attn_combine_kernel<<<(ROWS * 16 + 255) / 256, 256>>>((float*)d_out);
}

// round 5
// speedup vs baseline: 1.8536x; 1.8536x over previous
#include <cuda_runtime.h>
#include <cuda_bf16.h>
#include <math_constants.h>
#include <cstdint>

#define DM   1024
#define HS   64
#define BB   4
#define TT   2048
#define ROWS (BB * TT)        /* 8192 */
#define NS   16               /* key splits (SPLIT = q-tile = 128) */
#define SPLIT 128
#define KTILE 16
#define TRI  136              /* 16*17/2 active (qt,ks) pairs per batch */
#define NCOL 192              /* q|k|v fused output columns */

typedef unsigned long long u64;

/* ---------------- f32x2 packed math helpers (attention) ----------------- */
__device__ __forceinline__ void fma2(u64& d, u64 a, u64 b) {
    asm("fma.rn.f32x2 %0, %1, %2, %3;" : "=l"(d) : "l"(a), "l"(b), "l"(d));
}
__device__ __forceinline__ void mul2(u64& d, u64 a, u64 b) {
    asm("mul.rn.f32x2 %0, %1, %2;" : "=l"(d) : "l"(a), "l"(b));
}
__device__ __forceinline__ void add2(u64& d, u64 a, u64 b) {
    asm("add.rn.f32x2 %0, %1, %2;" : "=l"(d) : "l"(a), "l"(b));
}
__device__ __forceinline__ u64 dup2(float x) {
    u64 r; unsigned u = __float_as_uint(x);
    asm("mov.b64 %0, {%1, %1};" : "=l"(r) : "r"(u));
    return r;
}
__device__ __forceinline__ float2 unpk(u64 v) {
    unsigned lo, hi;
    asm("mov.b64 {%0, %1}, %2;" : "=r"(lo), "=r"(hi) : "l"(v));
    return make_float2(__uint_as_float(lo), __uint_as_float(hi));
}
__device__ __forceinline__ unsigned pk_bf2(float a, float b) {  /* lo=a, hi=b */
    unsigned r;
    asm("cvt.rn.bf16x2.f32 %0, %1, %2;" : "=r"(r) : "f"(b), "f"(a));
    return r;
}

/* ---------------- mma.sync bf16 m16n8k16 (fallback HMMA path) ----------- */
__device__ __forceinline__ void mma_bf16(float* d, const unsigned* a, const unsigned* b) {
    asm volatile(
        "mma.sync.aligned.m16n8k16.row.col.f32.bf16.bf16.f32 "
        "{%0,%1,%2,%3}, {%4,%5,%6,%7}, {%8,%9}, {%0,%1,%2,%3};"
        : "+f"(d[0]), "+f"(d[1]), "+f"(d[2]), "+f"(d[3])
        : "r"(a[0]), "r"(a[1]), "r"(a[2]), "r"(a[3]), "r"(b[0]), "r"(b[1]));
}

/* ---------------- device scratch ---------------------------------------- */
__device__ u64 g_xh[ROWS * DM / 4];          /* x hi, bf16 packed 4/u64 */
__device__ u64 g_xl[ROWS * DM / 4];          /* x lo */
__device__ u64 g_Bh[NCOL * DM / 4];          /* W^T fused [192][1024] hi */
__device__ u64 g_Bl[NCOL * DM / 4];
__device__ float g_q[ROWS * HS];
__device__ float g_k[ROWS * HS];
__device__ float g_v[ROWS * HS];
__device__ float g_po[(size_t)NS * ROWS * HS];
__device__ float g_pm[NS * ROWS];
__device__ float g_pl[NS * ROWS];

/* ---------------- split x into bf16 hi/lo -------------------------------- */
__global__ __launch_bounds__(256)
void split_x_kernel(const float* __restrict__ x) {
    int i = blockIdx.x * 256 + threadIdx.x;           /* float4 index */
    float4 v = ((const float4*)x)[i];
    float h0 = __bfloat162float(__float2bfloat16(v.x));
    float h1 = __bfloat162float(__float2bfloat16(v.y));
    float h2 = __bfloat162float(__float2bfloat16(v.z));
    float h3 = __bfloat162float(__float2bfloat16(v.w));
    unsigned ph0 = pk_bf2(h0, h1), ph1 = pk_bf2(h2, h3);
    unsigned pl0 = pk_bf2(v.x - h0, v.y - h1), pl1 = pk_bf2(v.z - h2, v.w - h3);
    g_xh[i] = ((u64)ph1 << 32) | ph0;
    g_xl[i] = ((u64)pl1 << 32) | pl0;
}

/* ---------------- build fused transposed weight B[n][k] ------------------ */
__global__ __launch_bounds__(256)
void build_b_kernel(const float* __restrict__ Wq, const float* __restrict__ Wk,
                    const float* __restrict__ Wv) {
    int i = blockIdx.x * 256 + threadIdx.x;           /* n*1024 + k */
    int n = i >> 10, k = i & 1023;
    const float* W = (n < 64) ? Wq : ((n < 128) ? Wk : Wv);
    float v = W[(size_t)k * HS + (n & 63)];
    float h = __bfloat162float(__float2bfloat16(v));
    ((__nv_bfloat16*)g_Bh)[i] = __float2bfloat16(h);
    ((__nv_bfloat16*)g_Bl)[i] = __float2bfloat16(v - h);
}

/* ---------------- QKV GEMM via mma.sync bf16 (hi/lo split) ---------------
 * Block: 256 thr (8 warps, 4m x 2n), tile M=128 N=64, K chunks of 32.
 * Smem rows padded to 80B -> conflict-free fragment LDS.
 * grid = (64, 3): blockIdx.y selects q/k/v output + bias. */
#define APITCH 80
__global__ __launch_bounds__(256)
void qkv_mma_kernel(const float* __restrict__ bq, const float* __restrict__ bk) {
    __shared__ __align__(16) uint8_t sAh[128 * APITCH];
    __shared__ __align__(16) uint8_t sAl[128 * APITCH];
    __shared__ __align__(16) uint8_t sBh[64 * APITCH];
    __shared__ __align__(16) uint8_t sBl[64 * APITCH];

    const int tid   = threadIdx.x;
    const int which = blockIdx.y;
    const int row0  = blockIdx.x * 128;
    const int w     = tid >> 5;
    const int lane  = tid & 31;
    const int wm    = w & 3;             /* m group: 32 rows   */
    const int wn    = w >> 2;            /* n group: 32 cols   */
    const int g     = lane >> 2;
    const int tig   = lane & 3;

    /* loader assignments (u64 = 4 bf16) */
    int ar[4], aj[4], br[2], bj[2];
    #pragma unroll
    for (int t = 0; t < 4; t++) { int i = tid + t * 256; ar[t] = i >> 3; aj[t] = i & 7; }
    #pragma unroll
    for (int t = 0; t < 2; t++) { int i = tid + t * 256; br[t] = i >> 3; bj[t] = i & 7; }

    float acc[2][4][4];
    #pragma unroll
    for (int mt = 0; mt < 2; mt++)
        #pragma unroll
        for (int nt = 0; nt < 4; nt++)
            #pragma unroll
            for (int e = 0; e < 4; e++) acc[mt][nt][e] = 0.f;

    u64 rah[4], ral[4], rbh[2], rbl[2];
    /* prefetch chunk 0 */
    #pragma unroll
    for (int t = 0; t < 4; t++) {
        size_t o = (size_t)(row0 + ar[t]) * 256 + aj[t];
        rah[t] = g_xh[o]; ral[t] = g_xl[o];
    }
    #pragma unroll
    for (int t = 0; t < 2; t++) {
        size_t o = (size_t)(which * 64 + br[t]) * 256 + bj[t];
        rbh[t] = g_Bh[o]; rbl[t] = g_Bl[o];
    }

    for (int c = 0; c < 32; c++) {
        /* store staged chunk */
        #pragma unroll
        for (int t = 0; t < 4; t++) {
            *(u64*)(sAh + ar[t] * APITCH + aj[t] * 8) = rah[t];
            *(u64*)(sAl + ar[t] * APITCH + aj[t] * 8) = ral[t];
        }
        #pragma unroll
        for (int t = 0; t < 2; t++) {
            *(u64*)(sBh + br[t] * APITCH + bj[t] * 8) = rbh[t];
            *(u64*)(sBl + br[t] * APITCH + bj[t] * 8) = rbl[t];
        }
        __syncthreads();

        if (c + 1 < 32) {                 /* prefetch next chunk */
            #pragma unroll
            for (int t = 0; t < 4; t++) {
                size_t o = (size_t)(row0 + ar[t]) * 256 + (c + 1) * 8 + aj[t];
                rah[t] = g_xh[o]; ral[t] = g_xl[o];
            }
            #pragma unroll
            for (int t = 0; t < 2; t++) {
                size_t o = (size_t)(which * 64 + br[t]) * 256 + (c + 1) * 8 + bj[t];
                rbh[t] = g_Bh[o]; rbl[t] = g_Bl[o];
            }
        }

        #pragma unroll
        for (int ks = 0; ks < 2; ks++) {
            unsigned ah[2][4], al[2][4], bh[4][2], bl[4][2];
            #pragma unroll
            for (int mt = 0; mt < 2; mt++) {
                int base = (wm * 32 + mt * 16 + g) * APITCH + ks * 32 + tig * 4;
                ah[mt][0] = *(const unsigned*)(sAh + base);
                ah[mt][1] = *(const unsigned*)(sAh + base + 8 * APITCH);
                ah[mt][2] = *(const unsigned*)(sAh + base + 16);
                ah[mt][3] = *(const unsigned*)(sAh + base + 8 * APITCH + 16);
                al[mt][0] = *(const unsigned*)(sAl + base);
                al[mt][1] = *(const unsigned*)(sAl + base + 8 * APITCH);
                al[mt][2] = *(const unsigned*)(sAl + base + 16);
                al[mt][3] = *(const unsigned*)(sAl + base + 8 * APITCH + 16);
            }
            #pragma unroll
            for (int nt = 0; nt < 4; nt++) {
                int base = (wn * 32 + nt * 8 + g) * APITCH + ks * 32 + tig * 4;
                bh[nt][0] = *(const unsigned*)(sBh + base);
                bh[nt][1] = *(const unsigned*)(sBh + base + 16);
                bl[nt][0] = *(const unsigned*)(sBl + base);
                bl[nt][1] = *(const unsigned*)(sBl + base + 16);
            }
            #pragma unroll
            for (int mt = 0; mt < 2; mt++)
                #pragma unroll
                for (int nt = 0; nt < 4; nt++) {
                    mma_bf16(acc[mt][nt], ah[mt], bh[nt]);
                    mma_bf16(acc[mt][nt], ah[mt], bl[nt]);
                    mma_bf16(acc[mt][nt], al[mt], bh[nt]);
                }
        }
        __syncthreads();
    }

    /* epilogue */
    float* __restrict__ dst = (which == 0) ? g_q : ((which == 1) ? g_k : g_v);
    const float* bias = (which == 0) ? bq : ((which == 1) ? bk : nullptr);

    #pragma unroll
    for (int mt = 0; mt < 2; mt++) {
        #pragma unroll
        for (int nt = 0; nt < 4; nt++) {
            int m = row0 + wm * 32 + mt * 16 + g;
            int n = wn * 32 + nt * 8 + tig * 2;
            float2 bv = make_float2(0.f, 0.f);
            if (bias) { bv.x = bias[n]; bv.y = bias[n + 1]; }
            float2 v0, v1;
            v0.x = acc[mt][nt][0] + bv.x; v0.y = acc[mt][nt][1] + bv.y;
            v1.x = acc[mt][nt][2] + bv.x; v1.y = acc[mt][nt][3] + bv.y;
            *(float2*)&dst[(size_t)m * HS + n]       = v0;
            *(float2*)&dst[(size_t)(m + 8) * HS + n] = v1;
        }
    }
}

/* ---------------- causal flash-attention (round-2 form + diag skip) ------ */
__global__ __launch_bounds__(128)
void attn_split_kernel() {
    int t = blockIdx.x;
    int b = blockIdx.y;
    int qt = (int)((sqrtf(8.f * (float)t + 1.f) - 1.f) * 0.5f);
    while ((qt + 1) * (qt + 2) / 2 <= t) qt++;
    while (qt * (qt + 1) / 2 > t) qt--;
    int ks = t - qt * (qt + 1) / 2;

    const int tid  = threadIdx.x;
    const int r    = qt * SPLIT + tid;
    const int grow = b * TT + r;
    const int rmaxw = r | 31;              /* warp covers 32 consecutive rows */

    __shared__ float4 Ks[KTILE * 16];
    __shared__ float4 Vs[KTILE * 16];

    u64 q2[32];
    {
        const ulonglong2* qp = (const ulonglong2*)(g_q + (size_t)grow * HS);
        #pragma unroll
        for (int i = 0; i < 16; i++) {
            ulonglong2 v = qp[i];
            q2[2 * i] = v.x; q2[2 * i + 1] = v.y;
        }
    }

    u64 o2[32];
    #pragma unroll
    for (int i = 0; i < 32; i++) o2[i] = 0ull;
    float m = -CUDART_INF_F;
    float l = 0.f;

    for (int tile = 0; tile < SPLIT / KTILE; tile++) {
        const int j0 = ks * SPLIT + tile * KTILE;
        __syncthreads();
        {
            const float4* kp = (const float4*)(g_k + (size_t)(b * TT + j0) * HS);
            const float4* vp = (const float4*)(g_v + (size_t)(b * TT + j0) * HS);
            Ks[tid] = kp[tid]; Ks[tid + 128] = kp[tid + 128];
            Vs[tid] = vp[tid]; Vs[tid + 128] = vp[tid + 128];
        }
        __syncthreads();

        if (j0 > rmaxw) continue;          /* warp-uniform skip of masked tiles */

        const int jr = r - j0;
        float sc[KTILE];
        float tmax = -CUDART_INF_F;
        #pragma unroll
        for (int j = 0; j < KTILE; j++) {
            const ulonglong2* kk = (const ulonglong2*)&Ks[j * 16];
            u64 a0 = 0ull, a1 = 0ull, a2 = 0ull, a3 = 0ull;
            #pragma unroll
            for (int d = 0; d < 16; d += 2) {
                ulonglong2 kv0 = kk[d];
                fma2(a0, q2[2 * d + 0], kv0.x);
                fma2(a1, q2[2 * d + 1], kv0.y);
                ulonglong2 kv1 = kk[d + 1];
                fma2(a2, q2[2 * d + 2], kv1.x);
                fma2(a3, q2[2 * d + 3], kv1.y);
            }
            add2(a0, a0, a2);
            add2(a1, a1, a3);
            float2 u = unpk(a0);
            float2 w = unpk(a1);
            float s = ((u.x + u.y) + (w.x + w.y)) * 8.0f;   /* * sqrt(hs) per ref */
            sc[j] = (j <= jr) ? s : -CUDART_INF_F;
            tmax = fmaxf(tmax, sc[j]);
        }

        float mnew = fmaxf(m, tmax);
        float scale = __expf(m - mnew);
        m = mnew;
        l *= scale;
        u64 sd = dup2(scale);
        #pragma unroll
        for (int i = 0; i < 32; i++) mul2(o2[i], o2[i], sd);

        #pragma unroll
        for (int j = 0; j < KTILE; j++) {
            float p = __expf(sc[j] - mnew);
            l += p;
            u64 pd = dup2(p);
            const ulonglong2* vv = (const ulonglong2*)&Vs[j * 16];
            #pragma unroll
            for (int d = 0; d < 16; d++) {
                ulonglong2 w = vv[d];
                fma2(o2[2 * d + 0], pd, w.x);
                fma2(o2[2 * d + 1], pd, w.y);
            }
        }
    }

    g_pm[ks * ROWS + grow] = m;
    g_pl[ks * ROWS + grow] = l;
    ulonglong2* po = (ulonglong2*)(g_po + ((size_t)ks * ROWS + grow) * HS);
    #pragma unroll
    for (int i = 0; i < 16; i++) {
        ulonglong2 v; v.x = o2[2 * i]; v.y = o2[2 * i + 1];
        po[i] = v;
    }
}

/* ---------------- combine split partials -------------------------------- */
__global__ __launch_bounds__(256)
void attn_combine_kernel(float* __restrict__ out) {
    int t = blockIdx.x * blockDim.x + threadIdx.x;
    if (t >= ROWS * 16) return;
    int row = t >> 4;
    int d4  = t & 15;
    int smax = (row & (TT - 1)) >> 7;

    float m = -CUDART_INF_F;
    for (int s = 0; s <= smax; s++) m = fmaxf(m, g_pm[s * ROWS + row]);

    float l = 0.f;
    float4 acc = make_float4(0.f, 0.f, 0.f, 0.f);
    for (int s = 0; s <= smax; s++) {
        float w = __expf(g_pm[s * ROWS + row] - m);
        l += g_pl[s * ROWS + row] * w;
        float4 p = ((const float4*)g_po)[((size_t)s * ROWS + row) * 16 + d4];
        acc.x = fmaf(w, p.x, acc.x);
        acc.y = fmaf(w, p.y, acc.y);
        acc.z = fmaf(w, p.z, acc.z);
        acc.w = fmaf(w, p.w, acc.w);
    }
    float inv = 1.f / l;
    ((float4*)out)[(size_t)row * 16 + d4] =
        make_float4(acc.x * inv, acc.y * inv, acc.z * inv, acc.w * inv);
}

/* ---------------- launch ------------------------------------------------ */
extern "C" void kernel_launch(void* const* d_in, const int* in_sizes, int n_in,
                              void* d_out, int out_size) {
    (void)in_sizes; (void)n_in; (void)out_size;
    const float* x  = (const float*)d_in[0];
    const float* Wq = (const float*)d_in[1];
    const float* bq = (const float*)d_in[2];
    const float* Wk = (const float*)d_in[3];
    const float* bk = (const float*)d_in[4];
    const float* Wv = (const float*)d_in[5];

    split_x_kernel<<<ROWS * DM / 4 / 256, 256>>>(x);
    build_b_kernel<<<NCOL * DM / 256, 256>>>(Wq, Wk, Wv);
    qkv_mma_kernel<<<dim3(ROWS / 128, 3), 256>>>(bq, bk);
    attn_split_kernel<<<dim3(TRI, BB), 128>>>();
    attn_combine_kernel<<<(ROWS * 16 + 255) / 256, 256>>>((float*)d_out);
}

// round 6
// speedup vs baseline: 2.4936x; 1.3453x over previous
#include <cuda_runtime.h>
#include <cuda_bf16.h>
#include <math_constants.h>
#include <cstdint>

#define DM   1024
#define HS   64
#define BB   4
#define TT   2048
#define ROWS (BB * TT)        /* 8192 */
#define NS   16               /* key splits (SPLIT = q-tile = 128) */
#define SPLIT 128
#define TRI  136              /* 16*17/2 active (qt,ks) pairs per batch */
#define NCOL 192              /* q|k|v fused output columns */
#define SCV  11.541560327111707f   /* 8 * log2(e) */

typedef unsigned long long u64;

/* ---------------- helpers ------------------------------------------------ */
__device__ __forceinline__ unsigned pk_bf2(float a, float b) {  /* lo=a, hi=b */
    unsigned r;
    asm("cvt.rn.bf16x2.f32 %0, %1, %2;" : "=r"(r) : "f"(b), "f"(a));
    return r;
}
__device__ __forceinline__ void mma_bf16(float* d, const unsigned* a, const unsigned* b) {
    asm volatile(
        "mma.sync.aligned.m16n8k16.row.col.f32.bf16.bf16.f32 "
        "{%0,%1,%2,%3}, {%4,%5,%6,%7}, {%8,%9}, {%0,%1,%2,%3};"
        : "+f"(d[0]), "+f"(d[1]), "+f"(d[2]), "+f"(d[3])
        : "r"(a[0]), "r"(a[1]), "r"(a[2]), "r"(a[3]), "r"(b[0]), "r"(b[1]));
}

/* ---------------- device scratch ---------------------------------------- */
__device__ u64 g_xh[ROWS * DM / 4];          /* x hi, bf16 packed 4/u64 */
__device__ u64 g_xl[ROWS * DM / 4];          /* x lo */
__device__ u64 g_Bh[NCOL * DM / 4];          /* W^T fused [192][1024] hi */
__device__ u64 g_Bl[NCOL * DM / 4];
__device__ float g_q[ROWS * HS];
__device__ float g_k[ROWS * HS];
__device__ float g_v[ROWS * HS];
__device__ uint16_t g_qh[ROWS * HS], g_ql[ROWS * HS];   /* bf16 hi/lo */
__device__ uint16_t g_kh[ROWS * HS], g_kl[ROWS * HS];
__device__ uint16_t g_vth[BB * HS * TT], g_vtl[BB * HS * TT];  /* V transposed [b][d][t] */
__device__ float g_po[(size_t)NS * ROWS * HS];
__device__ float g_pm[NS * ROWS];
__device__ float g_pl[NS * ROWS];

/* ---------------- split x into bf16 hi/lo -------------------------------- */
__global__ __launch_bounds__(256)
void split_x_kernel(const float* __restrict__ x) {
    int i = blockIdx.x * 256 + threadIdx.x;           /* float4 index */
    float4 v = ((const float4*)x)[i];
    unsigned h01 = pk_bf2(v.x, v.y), h23 = pk_bf2(v.z, v.w);
    float h0 = __uint_as_float(h01 << 16);
    float h1 = __uint_as_float(h01 & 0xffff0000u);
    float h2 = __uint_as_float(h23 << 16);
    float h3 = __uint_as_float(h23 & 0xffff0000u);
    unsigned l01 = pk_bf2(v.x - h0, v.y - h1), l23 = pk_bf2(v.z - h2, v.w - h3);
    g_xh[i] = ((u64)h23 << 32) | h01;
    g_xl[i] = ((u64)l23 << 32) | l01;
}

/* ---------------- build fused transposed weight B[n][k] ------------------ */
__global__ __launch_bounds__(256)
void build_b_kernel(const float* __restrict__ Wq, const float* __restrict__ Wk,
                    const float* __restrict__ Wv) {
    int i = blockIdx.x * 256 + threadIdx.x;           /* n*1024 + k */
    int n = i >> 10, k = i & 1023;
    const float* W = (n < 64) ? Wq : ((n < 128) ? Wk : Wv);
    float v = W[(size_t)k * HS + (n & 63)];
    unsigned hp = pk_bf2(v, 0.f);
    float h = __uint_as_float(hp << 16);
    ((uint16_t*)g_Bh)[i] = (uint16_t)(hp & 0xffffu);
    unsigned lp = pk_bf2(v - h, 0.f);
    ((uint16_t*)g_Bl)[i] = (uint16_t)(lp & 0xffffu);
}

/* ---------------- QKV GEMM via mma.sync bf16 (hi/lo split) -------------- */
#define APITCH 80
__global__ __launch_bounds__(256)
void qkv_mma_kernel(const float* __restrict__ bq, const float* __restrict__ bk) {
    __shared__ __align__(16) uint8_t sAh[128 * APITCH];
    __shared__ __align__(16) uint8_t sAl[128 * APITCH];
    __shared__ __align__(16) uint8_t sBh[64 * APITCH];
    __shared__ __align__(16) uint8_t sBl[64 * APITCH];

    const int tid   = threadIdx.x;
    const int which = blockIdx.y;
    const int row0  = blockIdx.x * 128;
    const int w     = tid >> 5;
    const int lane  = tid & 31;
    const int wm    = w & 3;
    const int wn    = w >> 2;
    const int g     = lane >> 2;
    const int tig   = lane & 3;

    int ar[4], aj[4], br[2], bj[2];
    #pragma unroll
    for (int t = 0; t < 4; t++) { int i = tid + t * 256; ar[t] = i >> 3; aj[t] = i & 7; }
    #pragma unroll
    for (int t = 0; t < 2; t++) { int i = tid + t * 256; br[t] = i >> 3; bj[t] = i & 7; }

    float acc[2][4][4];
    #pragma unroll
    for (int mt = 0; mt < 2; mt++)
        #pragma unroll
        for (int nt = 0; nt < 4; nt++)
            #pragma unroll
            for (int e = 0; e < 4; e++) acc[mt][nt][e] = 0.f;

    u64 rah[4], ral[4], rbh[2], rbl[2];
    #pragma unroll
    for (int t = 0; t < 4; t++) {
        size_t o = (size_t)(row0 + ar[t]) * 256 + aj[t];
        rah[t] = g_xh[o]; ral[t] = g_xl[o];
    }
    #pragma unroll
    for (int t = 0; t < 2; t++) {
        size_t o = (size_t)(which * 64 + br[t]) * 256 + bj[t];
        rbh[t] = g_Bh[o]; rbl[t] = g_Bl[o];
    }

    for (int c = 0; c < 32; c++) {
        #pragma unroll
        for (int t = 0; t < 4; t++) {
            *(u64*)(sAh + ar[t] * APITCH + aj[t] * 8) = rah[t];
            *(u64*)(sAl + ar[t] * APITCH + aj[t] * 8) = ral[t];
        }
        #pragma unroll
        for (int t = 0; t < 2; t++) {
            *(u64*)(sBh + br[t] * APITCH + bj[t] * 8) = rbh[t];
            *(u64*)(sBl + br[t] * APITCH + bj[t] * 8) = rbl[t];
        }
        __syncthreads();

        if (c + 1 < 32) {
            #pragma unroll
            for (int t = 0; t < 4; t++) {
                size_t o = (size_t)(row0 + ar[t]) * 256 + (c + 1) * 8 + aj[t];
                rah[t] = g_xh[o]; ral[t] = g_xl[o];
            }
            #pragma unroll
            for (int t = 0; t < 2; t++) {
                size_t o = (size_t)(which * 64 + br[t]) * 256 + (c + 1) * 8 + bj[t];
                rbh[t] = g_Bh[o]; rbl[t] = g_Bl[o];
            }
        }

        #pragma unroll
        for (int ks = 0; ks < 2; ks++) {
            unsigned ah[2][4], al[2][4], bh[4][2], bl[4][2];
            #pragma unroll
            for (int mt = 0; mt < 2; mt++) {
                int base = (wm * 32 + mt * 16 + g) * APITCH + ks * 32 + tig * 4;
                ah[mt][0] = *(const unsigned*)(sAh + base);
                ah[mt][1] = *(const unsigned*)(sAh + base + 8 * APITCH);
                ah[mt][2] = *(const unsigned*)(sAh + base + 16);
                ah[mt][3] = *(const unsigned*)(sAh + base + 8 * APITCH + 16);
                al[mt][0] = *(const unsigned*)(sAl + base);
                al[mt][1] = *(const unsigned*)(sAl + base + 8 * APITCH);
                al[mt][2] = *(const unsigned*)(sAl + base + 16);
                al[mt][3] = *(const unsigned*)(sAl + base + 8 * APITCH + 16);
            }
            #pragma unroll
            for (int nt = 0; nt < 4; nt++) {
                int base = (wn * 32 + nt * 8 + g) * APITCH + ks * 32 + tig * 4;
                bh[nt][0] = *(const unsigned*)(sBh + base);
                bh[nt][1] = *(const unsigned*)(sBh + base + 16);
                bl[nt][0] = *(const unsigned*)(sBl + base);
                bl[nt][1] = *(const unsigned*)(sBl + base + 16);
            }
            #pragma unroll
            for (int mt = 0; mt < 2; mt++)
                #pragma unroll
                for (int nt = 0; nt < 4; nt++) {
                    mma_bf16(acc[mt][nt], ah[mt], bh[nt]);
                    mma_bf16(acc[mt][nt], ah[mt], bl[nt]);
                    mma_bf16(acc[mt][nt], al[mt], bh[nt]);
                }
        }
        __syncthreads();
    }

    float* __restrict__ dst = (which == 0) ? g_q : ((which == 1) ? g_k : g_v);
    const float* bias = (which == 0) ? bq : ((which == 1) ? bk : nullptr);

    #pragma unroll
    for (int mt = 0; mt < 2; mt++) {
        #pragma unroll
        for (int nt = 0; nt < 4; nt++) {
            int m = row0 + wm * 32 + mt * 16 + g;
            int n = wn * 32 + nt * 8 + tig * 2;
            float2 bv = make_float2(0.f, 0.f);
            if (bias) { bv.x = bias[n]; bv.y = bias[n + 1]; }
            float2 v0, v1;
            v0.x = acc[mt][nt][0] + bv.x; v0.y = acc[mt][nt][1] + bv.y;
            v1.x = acc[mt][nt][2] + bv.x; v1.y = acc[mt][nt][3] + bv.y;
            *(float2*)&dst[(size_t)m * HS + n]       = v0;
            *(float2*)&dst[(size_t)(m + 8) * HS + n] = v1;
        }
    }
}

/* ---------------- convert q,k fp32 -> bf16 hi/lo ------------------------- */
__global__ __launch_bounds__(256)
void conv_qk_kernel() {
    int i = blockIdx.x * 256 + threadIdx.x;           /* float4 index */
    const float* src = (blockIdx.y == 0) ? g_q : g_k;
    u64* dh = (u64*)((blockIdx.y == 0) ? g_qh : g_kh);
    u64* dl = (u64*)((blockIdx.y == 0) ? g_ql : g_kl);
    float4 v = ((const float4*)src)[i];
    unsigned h01 = pk_bf2(v.x, v.y), h23 = pk_bf2(v.z, v.w);
    float h0 = __uint_as_float(h01 << 16);
    float h1 = __uint_as_float(h01 & 0xffff0000u);
    float h2 = __uint_as_float(h23 << 16);
    float h3 = __uint_as_float(h23 & 0xffff0000u);
    unsigned l01 = pk_bf2(v.x - h0, v.y - h1), l23 = pk_bf2(v.z - h2, v.w - h3);
    dh[i] = ((u64)h23 << 32) | h01;
    dl[i] = ((u64)l23 << 32) | l01;
}

/* ---------------- convert + transpose V: [b][t][d] -> [b][d][t] ---------- */
__global__ __launch_bounds__(256)
void conv_vt_kernel() {
    __shared__ float s[32][33];
    const int t0 = blockIdx.x * 32;
    const int d0 = blockIdx.y * 32;
    const int b  = blockIdx.z;
    const int tx = threadIdx.x & 31;
    const int ty = threadIdx.x >> 5;
    #pragma unroll
    for (int r = ty; r < 32; r += 8)
        s[r][tx] = g_v[(size_t)(b * TT + t0 + r) * HS + d0 + tx];
    __syncthreads();
    #pragma unroll
    for (int r = ty; r < 32; r += 8) {
        float v = s[tx][r];
        unsigned hp = pk_bf2(v, 0.f);
        float h = __uint_as_float(hp << 16);
        unsigned lp = pk_bf2(v - h, 0.f);
        size_t o = (size_t)(b * HS + d0 + r) * TT + t0 + tx;
        g_vth[o] = (uint16_t)(hp & 0xffffu);
        g_vtl[o] = (uint16_t)(lp & 0xffffu);
    }
}

/* ---------------- causal flash-attention via mma.sync --------------------
 * 8 warps x m16 rows; 2 chunks of 64 keys per block (triangle split).
 * K, V^T staged in smem bf16 hi/lo, 144B pitch (conflict-free fragments).
 * P rebuilt from S accumulators in registers (FA2 layout identity). */
__global__ __launch_bounds__(256)
void attn_mma_kernel() {
    int t = blockIdx.x;
    int b = blockIdx.y;
    int qt = (int)((sqrtf(8.f * (float)t + 1.f) - 1.f) * 0.5f);
    while ((qt + 1) * (qt + 2) / 2 <= t) qt++;
    while (qt * (qt + 1) / 2 > t) qt--;
    int ks = t - qt * (qt + 1) / 2;

    const int tid  = threadIdx.x;
    const int w    = tid >> 5;
    const int lane = tid & 31;
    const int g    = lane >> 2;
    const int tig  = lane & 3;
    const int r0   = qt * 128 + w * 16;
    const int bT   = b * TT;

    __shared__ __align__(16) uint8_t sKh[64 * 144];
    __shared__ __align__(16) uint8_t sKl[64 * 144];
    __shared__ __align__(16) uint8_t sVh[64 * 144];
    __shared__ __align__(16) uint8_t sVl[64 * 144];

    /* Q fragments (held whole block) */
    unsigned qh[4][4], ql[4][4];
    {
        const uint16_t* qah = g_qh + (size_t)(bT + r0 + g) * HS;
        const uint16_t* qal = g_ql + (size_t)(bT + r0 + g) * HS;
        #pragma unroll
        for (int kq = 0; kq < 4; kq++) {
            int c = kq * 16 + 2 * tig;
            qh[kq][0] = *(const unsigned*)(qah + c);
            qh[kq][1] = *(const unsigned*)(qah + 8 * HS + c);
            qh[kq][2] = *(const unsigned*)(qah + c + 8);
            qh[kq][3] = *(const unsigned*)(qah + 8 * HS + c + 8);
            ql[kq][0] = *(const unsigned*)(qal + c);
            ql[kq][1] = *(const unsigned*)(qal + 8 * HS + c);
            ql[kq][2] = *(const unsigned*)(qal + c + 8);
            ql[kq][3] = *(const unsigned*)(qal + 8 * HS + c + 8);
        }
    }

    float o[8][4];
    #pragma unroll
    for (int i = 0; i < 8; i++)
        #pragma unroll
        for (int e = 0; e < 4; e++) o[i][e] = 0.f;
    float m_a = -CUDART_INF_F, m_b = -CUDART_INF_F;
    float l_a = 0.f, l_b = 0.f;
    const int ra = r0 + g, rb = r0 + g + 8;

    for (int c2 = 0; c2 < 2; c2++) {
        const int j0 = ks * SPLIT + c2 * 64;
        __syncthreads();
        #pragma unroll
        for (int t4 = 0; t4 < 4; t4++) {
            int i = tid + t4 * 256;
            int row = i >> 4, c8 = i & 15;
            *(u64*)(sKh + row * 144 + c8 * 8) =
                *(const u64*)(g_kh + (size_t)(bT + j0 + row) * HS + c8 * 4);
            *(u64*)(sKl + row * 144 + c8 * 8) =
                *(const u64*)(g_kl + (size_t)(bT + j0 + row) * HS + c8 * 4);
            *(u64*)(sVh + row * 144 + c8 * 8) =
                *(const u64*)(g_vth + (size_t)(b * HS + row) * TT + j0 + c8 * 4);
            *(u64*)(sVl + row * 144 + c8 * 8) =
                *(const u64*)(g_vtl + (size_t)(b * HS + row) * TT + j0 + c8 * 4);
        }
        __syncthreads();

        if (j0 > r0 + 15) continue;       /* warp-uniform skip */

        /* ---- S = Q K^T (3-pass hi/lo) ---- */
        float sc[8][4];
        #pragma unroll
        for (int nt = 0; nt < 8; nt++)
            #pragma unroll
            for (int e = 0; e < 4; e++) sc[nt][e] = 0.f;

        #pragma unroll
        for (int nt = 0; nt < 8; nt++) {
            #pragma unroll
            for (int kk = 0; kk < 4; kk++) {
                int off = (nt * 8 + g) * 144 + (kk * 16 + 2 * tig) * 2;
                unsigned bh[2], bl[2];
                bh[0] = *(const unsigned*)(sKh + off);
                bh[1] = *(const unsigned*)(sKh + off + 16);
                bl[0] = *(const unsigned*)(sKl + off);
                bl[1] = *(const unsigned*)(sKl + off + 16);
                mma_bf16(sc[nt], qh[kk], bh);
                mma_bf16(sc[nt], qh[kk], bl);
                mma_bf16(sc[nt], ql[kk], bh);
            }
        }

        /* ---- mask + online softmax ---- */
        float mxa = -CUDART_INF_F, mxb = -CUDART_INF_F;
        #pragma unroll
        for (int nt = 0; nt < 8; nt++) {
            int jc = j0 + nt * 8 + 2 * tig;
            if (jc     > ra) sc[nt][0] = -CUDART_INF_F;
            if (jc + 1 > ra) sc[nt][1] = -CUDART_INF_F;
            if (jc     > rb) sc[nt][2] = -CUDART_INF_F;
            if (jc + 1 > rb) sc[nt][3] = -CUDART_INF_F;
            mxa = fmaxf(mxa, fmaxf(sc[nt][0], sc[nt][1]));
            mxb = fmaxf(mxb, fmaxf(sc[nt][2], sc[nt][3]));
        }
        mxa = fmaxf(mxa, __shfl_xor_sync(0xffffffffu, mxa, 1));
        mxa = fmaxf(mxa, __shfl_xor_sync(0xffffffffu, mxa, 2));
        mxb = fmaxf(mxb, __shfl_xor_sync(0xffffffffu, mxb, 1));
        mxb = fmaxf(mxb, __shfl_xor_sync(0xffffffffu, mxb, 2));

        float mna = fmaxf(m_a, mxa), mnb = fmaxf(m_b, mxb);
        float alpha_a = exp2f((m_a - mna) * SCV);
        float alpha_b = exp2f((m_b - mnb) * SCV);
        m_a = mna; m_b = mnb;

        float p[8][4];
        float laa = 0.f, lba = 0.f;
        #pragma unroll
        for (int nt = 0; nt < 8; nt++) {
            p[nt][0] = exp2f((sc[nt][0] - mna) * SCV);
            p[nt][1] = exp2f((sc[nt][1] - mna) * SCV);
            p[nt][2] = exp2f((sc[nt][2] - mnb) * SCV);
            p[nt][3] = exp2f((sc[nt][3] - mnb) * SCV);
            laa += p[nt][0] + p[nt][1];
            lba += p[nt][2] + p[nt][3];
        }
        laa += __shfl_xor_sync(0xffffffffu, laa, 1);
        laa += __shfl_xor_sync(0xffffffffu, laa, 2);
        lba += __shfl_xor_sync(0xffffffffu, lba, 1);
        lba += __shfl_xor_sync(0xffffffffu, lba, 2);
        l_a = l_a * alpha_a + laa;
        l_b = l_b * alpha_b + lba;

        #pragma unroll
        for (int nt = 0; nt < 8; nt++) {
            o[nt][0] *= alpha_a; o[nt][1] *= alpha_a;
            o[nt][2] *= alpha_b; o[nt][3] *= alpha_b;
        }

        /* ---- P fragments (register-only, hi/lo) ---- */
        unsigned ph[4][4], pl[4][4];
        #pragma unroll
        for (int k2 = 0; k2 < 4; k2++) {
            int n0 = 2 * k2, n1 = 2 * k2 + 1;
            #pragma unroll
            for (int e = 0; e < 4; e++) {
                int nt = (e < 2) ? n0 : n1;
                int e0 = (e & 1) ? 2 : 0;      /* e:0 rowA n0, 1 rowB n0, 2 rowA n1, 3 rowB n1 */
                float pa = p[nt][e0], pb = p[nt][e0 + 1];
                unsigned hp = pk_bf2(pa, pb);
                float ha = __uint_as_float(hp << 16);
                float hb = __uint_as_float(hp & 0xffff0000u);
                ph[k2][e] = hp;
                pl[k2][e] = pk_bf2(pa - ha, pb - hb);
            }
        }

        /* ---- O += P V ---- */
        #pragma unroll
        for (int nt = 0; nt < 8; nt++) {
            #pragma unroll
            for (int k2 = 0; k2 < 4; k2++) {
                int off = (nt * 8 + g) * 144 + (k2 * 16 + 2 * tig) * 2;
                unsigned vh[2], vl[2];
                vh[0] = *(const unsigned*)(sVh + off);
                vh[1] = *(const unsigned*)(sVh + off + 16);
                vl[0] = *(const unsigned*)(sVl + off);
                vl[1] = *(const unsigned*)(sVl + off + 16);
                mma_bf16(o[nt], ph[k2], vh);
                mma_bf16(o[nt], ph[k2], vl);
                mma_bf16(o[nt], pl[k2], vh);
            }
        }
    }

    /* write partials */
    size_t pa_off = ((size_t)ks * ROWS + bT + ra) * HS;
    size_t pb_off = ((size_t)ks * ROWS + bT + rb) * HS;
    #pragma unroll
    for (int nt = 0; nt < 8; nt++) {
        *(float2*)&g_po[pa_off + nt * 8 + 2 * tig] = make_float2(o[nt][0], o[nt][1]);
        *(float2*)&g_po[pb_off + nt * 8 + 2 * tig] = make_float2(o[nt][2], o[nt][3]);
    }
    if (tig == 0) {
        g_pm[ks * ROWS + bT + ra] = m_a * 8.0f;
        g_pl[ks * ROWS + bT + ra] = l_a;
        g_pm[ks * ROWS + bT + rb] = m_b * 8.0f;
        g_pl[ks * ROWS + bT + rb] = l_b;
    }
}

/* ---------------- combine split partials -------------------------------- */
__global__ __launch_bounds__(256)
void attn_combine_kernel(float* __restrict__ out) {
    int t = blockIdx.x * blockDim.x + threadIdx.x;
    if (t >= ROWS * 16) return;
    int row = t >> 4;
    int d4  = t & 15;
    int smax = (row & (TT - 1)) >> 7;

    float m = -CUDART_INF_F;
    for (int s = 0; s <= smax; s++) m = fmaxf(m, g_pm[s * ROWS + row]);

    float l = 0.f;
    float4 acc = make_float4(0.f, 0.f, 0.f, 0.f);
    for (int s = 0; s <= smax; s++) {
        float wgt = __expf(g_pm[s * ROWS + row] - m);
        l += g_pl[s * ROWS + row] * wgt;
        float4 p = ((const float4*)g_po)[((size_t)s * ROWS + row) * 16 + d4];
        acc.x = fmaf(wgt, p.x, acc.x);
        acc.y = fmaf(wgt, p.y, acc.y);
        acc.z = fmaf(wgt, p.z, acc.z);
        acc.w = fmaf(wgt, p.w, acc.w);
    }
    float inv = 1.f / l;
    ((float4*)out)[(size_t)row * 16 + d4] =
        make_float4(acc.x * inv, acc.y * inv, acc.z * inv, acc.w * inv);
}

/* ---------------- launch ------------------------------------------------ */
extern "C" void kernel_launch(void* const* d_in, const int* in_sizes, int n_in,
                              void* d_out, int out_size) {
    (void)in_sizes; (void)n_in; (void)out_size;
    const float* x  = (const float*)d_in[0];
    const float* Wq = (const float*)d_in[1];
    const float* bq = (const float*)d_in[2];
    const float* Wk = (const float*)d_in[3];
    const float* bk = (const float*)d_in[4];
    const float* Wv = (const float*)d_in[5];

    split_x_kernel<<<ROWS * DM / 4 / 256, 256>>>(x);
    build_b_kernel<<<NCOL * DM / 256, 256>>>(Wq, Wk, Wv);
    qkv_mma_kernel<<<dim3(ROWS / 128, 3), 256>>>(bq, bk);
    conv_qk_kernel<<<dim3(ROWS * HS / 4 / 256, 2), 256>>>();
    conv_vt_kernel<<<dim3(TT / 32, HS / 32, BB), 256>>>();
    attn_mma_kernel<<<dim3(TRI, BB), 256>>>();
    attn_combine_kernel<<<(ROWS * 16 + 255) / 256, 256>>>((float*)d_out);
}

// round 7
// speedup vs baseline: 2.9966x; 1.2017x over previous
#include <cuda_runtime.h>
#include <cuda_bf16.h>
#include <math_constants.h>
#include <cstdint>

#define DM   1024
#define HS   64
#define BB   4
#define TT   2048
#define ROWS (BB * TT)        /* 8192 */
#define NS   16               /* key splits (SPLIT = q-tile = 128) */
#define SPLIT 128
#define TRI  136              /* 16*17/2 active (qt,ks) pairs per batch */
#define NCOL 192              /* q|k|v fused output columns */
#define SCV  11.541560327111707f   /* 8 * log2(e) */

typedef unsigned long long u64;

/* ---------------- helpers ------------------------------------------------ */
__device__ __forceinline__ unsigned pk_bf2(float a, float b) {  /* lo=a, hi=b */
    unsigned r;
    asm("cvt.rn.bf16x2.f32 %0, %1, %2;" : "=r"(r) : "f"(b), "f"(a));
    return r;
}
__device__ __forceinline__ void mma_bf16(float* d, const unsigned* a, const unsigned* b) {
    asm volatile(
        "mma.sync.aligned.m16n8k16.row.col.f32.bf16.bf16.f32 "
        "{%0,%1,%2,%3}, {%4,%5,%6,%7}, {%8,%9}, {%0,%1,%2,%3};"
        : "+f"(d[0]), "+f"(d[1]), "+f"(d[2]), "+f"(d[3])
        : "r"(a[0]), "r"(a[1]), "r"(a[2]), "r"(a[3]), "r"(b[0]), "r"(b[1]));
}
/* split float4 -> packed bf16 hi u64 + lo u64 */
__device__ __forceinline__ void split4(float4 v, u64& hi, u64& lo) {
    unsigned h01 = pk_bf2(v.x, v.y), h23 = pk_bf2(v.z, v.w);
    float h0 = __uint_as_float(h01 << 16);
    float h1 = __uint_as_float(h01 & 0xffff0000u);
    float h2 = __uint_as_float(h23 << 16);
    float h3 = __uint_as_float(h23 & 0xffff0000u);
    unsigned l01 = pk_bf2(v.x - h0, v.y - h1), l23 = pk_bf2(v.z - h2, v.w - h3);
    hi = ((u64)h23 << 32) | h01;
    lo = ((u64)l23 << 32) | l01;
}

/* ---------------- device scratch ---------------------------------------- */
__device__ u64 g_Bh[NCOL * DM / 4];          /* W^T fused [192][1024] hi */
__device__ u64 g_Bl[NCOL * DM / 4];
__device__ uint16_t g_qh[ROWS * HS], g_ql[ROWS * HS];   /* bf16 hi/lo */
__device__ uint16_t g_kh[ROWS * HS], g_kl[ROWS * HS];
__device__ uint16_t g_vth[BB * HS * TT], g_vtl[BB * HS * TT];  /* V^T [b][d][t] */
__device__ float g_po[(size_t)NS * ROWS * HS];
__device__ float g_pm[NS * ROWS];
__device__ float g_pl[NS * ROWS];

/* ---------------- build fused transposed weight B[n][k] ------------------ */
__global__ __launch_bounds__(256)
void build_b_kernel(const float* __restrict__ Wq, const float* __restrict__ Wk,
                    const float* __restrict__ Wv) {
    int i = blockIdx.x * 256 + threadIdx.x;           /* n*1024 + k */
    int n = i >> 10, k = i & 1023;
    const float* W = (n < 64) ? Wq : ((n < 128) ? Wk : Wv);
    float v = W[(size_t)k * HS + (n & 63)];
    unsigned hp = pk_bf2(v, 0.f);
    float h = __uint_as_float(hp << 16);
    unsigned lp = pk_bf2(v - h, 0.f);
    ((uint16_t*)g_Bh)[i] = (uint16_t)(hp & 0xffffu);
    ((uint16_t*)g_Bl)[i] = (uint16_t)(lp & 0xffffu);
}

/* ---------------- QKV GEMM via mma.sync bf16 (hi/lo split) ---------------
 * Loads fp32 x directly (in-register bf16 split), writes q/k as bf16 hi/lo,
 * writes V transposed as bf16 hi/lo via smem transpose (aliased buffers). */
#define APITCH 80
#define TPITCH 132
__global__ __launch_bounds__(256)
void qkv_mma_kernel(const float* __restrict__ x,
                    const float* __restrict__ bq, const float* __restrict__ bk) {
    /* union: main loop tiles (30720 B)  |  V epilogue transpose (33792 B) */
    __shared__ __align__(16) uint8_t sbuf[64 * TPITCH * 4];
    uint8_t* sAh = sbuf;                       /* 128*80 = 10240 */
    uint8_t* sAl = sbuf + 10240;               /* 10240 */
    uint8_t* sBh = sbuf + 20480;               /* 64*80 = 5120 */
    uint8_t* sBl = sbuf + 25600;               /* 5120  */
    float*   sT  = (float*)sbuf;               /* 64 x TPITCH fp32 */

    const int tid   = threadIdx.x;
    const int which = blockIdx.y;
    const int row0  = blockIdx.x * 128;
    const int w     = tid >> 5;
    const int lane  = tid & 31;
    const int wm    = w & 3;
    const int wn    = w >> 2;
    const int g     = lane >> 2;
    const int tig   = lane & 3;

    int ar[4], aj[4], br[2], bj[2];
    #pragma unroll
    for (int t = 0; t < 4; t++) { int i = tid + t * 256; ar[t] = i >> 3; aj[t] = i & 7; }
    #pragma unroll
    for (int t = 0; t < 2; t++) { int i = tid + t * 256; br[t] = i >> 3; bj[t] = i & 7; }

    float acc[2][4][4];
    #pragma unroll
    for (int mt = 0; mt < 2; mt++)
        #pragma unroll
        for (int nt = 0; nt < 4; nt++)
            #pragma unroll
            for (int e = 0; e < 4; e++) acc[mt][nt][e] = 0.f;

    float4 fa[4];
    u64 rbh[2], rbl[2];
    #pragma unroll
    for (int t = 0; t < 4; t++)
        fa[t] = *(const float4*)(x + (size_t)(row0 + ar[t]) * DM + aj[t] * 4);
    #pragma unroll
    for (int t = 0; t < 2; t++) {
        size_t o = (size_t)(which * 64 + br[t]) * 256 + bj[t];
        rbh[t] = g_Bh[o]; rbl[t] = g_Bl[o];
    }

    for (int c = 0; c < 32; c++) {
        #pragma unroll
        for (int t = 0; t < 4; t++) {
            u64 hi, lo;
            split4(fa[t], hi, lo);
            *(u64*)(sAh + ar[t] * APITCH + aj[t] * 8) = hi;
            *(u64*)(sAl + ar[t] * APITCH + aj[t] * 8) = lo;
        }
        #pragma unroll
        for (int t = 0; t < 2; t++) {
            *(u64*)(sBh + br[t] * APITCH + bj[t] * 8) = rbh[t];
            *(u64*)(sBl + br[t] * APITCH + bj[t] * 8) = rbl[t];
        }
        __syncthreads();

        if (c + 1 < 32) {
            #pragma unroll
            for (int t = 0; t < 4; t++)
                fa[t] = *(const float4*)(x + (size_t)(row0 + ar[t]) * DM
                                           + (c + 1) * 32 + aj[t] * 4);
            #pragma unroll
            for (int t = 0; t < 2; t++) {
                size_t o = (size_t)(which * 64 + br[t]) * 256 + (c + 1) * 8 + bj[t];
                rbh[t] = g_Bh[o]; rbl[t] = g_Bl[o];
            }
        }

        #pragma unroll
        for (int ks = 0; ks < 2; ks++) {
            unsigned ah[2][4], al[2][4], bh[4][2], bl[4][2];
            #pragma unroll
            for (int mt = 0; mt < 2; mt++) {
                int base = (wm * 32 + mt * 16 + g) * APITCH + ks * 32 + tig * 4;
                ah[mt][0] = *(const unsigned*)(sAh + base);
                ah[mt][1] = *(const unsigned*)(sAh + base + 8 * APITCH);
                ah[mt][2] = *(const unsigned*)(sAh + base + 16);
                ah[mt][3] = *(const unsigned*)(sAh + base + 8 * APITCH + 16);
                al[mt][0] = *(const unsigned*)(sAl + base);
                al[mt][1] = *(const unsigned*)(sAl + base + 8 * APITCH);
                al[mt][2] = *(const unsigned*)(sAl + base + 16);
                al[mt][3] = *(const unsigned*)(sAl + base + 8 * APITCH + 16);
            }
            #pragma unroll
            for (int nt = 0; nt < 4; nt++) {
                int base = (wn * 32 + nt * 8 + g) * APITCH + ks * 32 + tig * 4;
                bh[nt][0] = *(const unsigned*)(sBh + base);
                bh[nt][1] = *(const unsigned*)(sBh + base + 16);
                bl[nt][0] = *(const unsigned*)(sBl + base);
                bl[nt][1] = *(const unsigned*)(sBl + base + 16);
            }
            #pragma unroll
            for (int mt = 0; mt < 2; mt++)
                #pragma unroll
                for (int nt = 0; nt < 4; nt++) {
                    mma_bf16(acc[mt][nt], ah[mt], bh[nt]);
                    mma_bf16(acc[mt][nt], ah[mt], bl[nt]);
                    mma_bf16(acc[mt][nt], al[mt], bh[nt]);
                }
        }
        __syncthreads();
    }

    if (which < 2) {
        /* q/k epilogue: bias + pack to bf16 hi/lo directly */
        uint16_t* dh = (which == 0) ? g_qh : g_kh;
        uint16_t* dl = (which == 0) ? g_ql : g_kl;
        const float* bias = (which == 0) ? bq : bk;
        #pragma unroll
        for (int mt = 0; mt < 2; mt++) {
            #pragma unroll
            for (int nt = 0; nt < 4; nt++) {
                int m = row0 + wm * 32 + mt * 16 + g;
                int n = wn * 32 + nt * 8 + tig * 2;
                float bx = bias[n], by = bias[n + 1];
                float v0x = acc[mt][nt][0] + bx, v0y = acc[mt][nt][1] + by;
                float v1x = acc[mt][nt][2] + bx, v1y = acc[mt][nt][3] + by;
                unsigned h0 = pk_bf2(v0x, v0y);
                unsigned h1 = pk_bf2(v1x, v1y);
                float h0x = __uint_as_float(h0 << 16);
                float h0y = __uint_as_float(h0 & 0xffff0000u);
                float h1x = __uint_as_float(h1 << 16);
                float h1y = __uint_as_float(h1 & 0xffff0000u);
                *(unsigned*)&dh[(size_t)m * HS + n]        = h0;
                *(unsigned*)&dl[(size_t)m * HS + n]        = pk_bf2(v0x - h0x, v0y - h0y);
                *(unsigned*)&dh[(size_t)(m + 8) * HS + n]  = h1;
                *(unsigned*)&dl[(size_t)(m + 8) * HS + n]  = pk_bf2(v1x - h1x, v1y - h1y);
            }
        }
    } else {
        /* V epilogue: transpose via smem, write V^T bf16 hi/lo coalesced */
        #pragma unroll
        for (int mt = 0; mt < 2; mt++) {
            #pragma unroll
            for (int nt = 0; nt < 4; nt++) {
                int ml = wm * 32 + mt * 16 + g;         /* local row 0..127 */
                int n  = wn * 32 + nt * 8 + tig * 2;
                sT[n * TPITCH + ml]             = acc[mt][nt][0];
                sT[(n + 1) * TPITCH + ml]       = acc[mt][nt][1];
                sT[n * TPITCH + ml + 8]         = acc[mt][nt][2];
                sT[(n + 1) * TPITCH + ml + 8]   = acc[mt][nt][3];
            }
        }
        __syncthreads();
        const int b  = row0 >> 11;
        const int t0 = row0 & (TT - 1);
        #pragma unroll
        for (int t4 = 0; t4 < 8; t4++) {
            int idx = tid + t4 * 256;          /* 0..2047 */
            int d = idx >> 5, j = idx & 31;
            float4 v = *(const float4*)&sT[d * TPITCH + 4 * j];
            u64 hi, lo;
            split4(v, hi, lo);
            size_t o = ((size_t)(b * HS + d)) * TT + t0 + 4 * j;
            *(u64*)&g_vth[o] = hi;
            *(u64*)&g_vtl[o] = lo;
        }
    }
}

/* ---------------- causal flash-attention via mma.sync -------------------- */
__global__ __launch_bounds__(256)
void attn_mma_kernel() {
    int t = blockIdx.x;
    int b = blockIdx.y;
    int qt = (int)((sqrtf(8.f * (float)t + 1.f) - 1.f) * 0.5f);
    while ((qt + 1) * (qt + 2) / 2 <= t) qt++;
    while (qt * (qt + 1) / 2 > t) qt--;
    int ks = t - qt * (qt + 1) / 2;

    const int tid  = threadIdx.x;
    const int w    = tid >> 5;
    const int lane = tid & 31;
    const int g    = lane >> 2;
    const int tig  = lane & 3;
    const int r0   = qt * 128 + w * 16;
    const int bT   = b * TT;

    __shared__ __align__(16) uint8_t sKh[64 * 144];
    __shared__ __align__(16) uint8_t sKl[64 * 144];
    __shared__ __align__(16) uint8_t sVh[64 * 144];
    __shared__ __align__(16) uint8_t sVl[64 * 144];

    unsigned qh[4][4], ql[4][4];
    {
        const uint16_t* qah = g_qh + (size_t)(bT + r0 + g) * HS;
        const uint16_t* qal = g_ql + (size_t)(bT + r0 + g) * HS;
        #pragma unroll
        for (int kq = 0; kq < 4; kq++) {
            int c = kq * 16 + 2 * tig;
            qh[kq][0] = *(const unsigned*)(qah + c);
            qh[kq][1] = *(const unsigned*)(qah + 8 * HS + c);
            qh[kq][2] = *(const unsigned*)(qah + c + 8);
            qh[kq][3] = *(const unsigned*)(qah + 8 * HS + c + 8);
            ql[kq][0] = *(const unsigned*)(qal + c);
            ql[kq][1] = *(const unsigned*)(qal + 8 * HS + c);
            ql[kq][2] = *(const unsigned*)(qal + c + 8);
            ql[kq][3] = *(const unsigned*)(qal + 8 * HS + c + 8);
        }
    }

    float o[8][4];
    #pragma unroll
    for (int i = 0; i < 8; i++)
        #pragma unroll
        for (int e = 0; e < 4; e++) o[i][e] = 0.f;
    float m_a = -CUDART_INF_F, m_b = -CUDART_INF_F;
    float l_a = 0.f, l_b = 0.f;
    const int ra = r0 + g, rb = r0 + g + 8;

    for (int c2 = 0; c2 < 2; c2++) {
        const int j0 = ks * SPLIT + c2 * 64;
        __syncthreads();
        #pragma unroll
        for (int t4 = 0; t4 < 4; t4++) {
            int i = tid + t4 * 256;
            int row = i >> 4, c8 = i & 15;
            *(u64*)(sKh + row * 144 + c8 * 8) =
                *(const u64*)(g_kh + (size_t)(bT + j0 + row) * HS + c8 * 4);
            *(u64*)(sKl + row * 144 + c8 * 8) =
                *(const u64*)(g_kl + (size_t)(bT + j0 + row) * HS + c8 * 4);
            *(u64*)(sVh + row * 144 + c8 * 8) =
                *(const u64*)(g_vth + (size_t)(b * HS + row) * TT + j0 + c8 * 4);
            *(u64*)(sVl + row * 144 + c8 * 8) =
                *(const u64*)(g_vtl + (size_t)(b * HS + row) * TT + j0 + c8 * 4);
        }
        __syncthreads();

        if (j0 > r0 + 15) continue;

        float sc[8][4];
        #pragma unroll
        for (int nt = 0; nt < 8; nt++)
            #pragma unroll
            for (int e = 0; e < 4; e++) sc[nt][e] = 0.f;

        #pragma unroll
        for (int nt = 0; nt < 8; nt++) {
            #pragma unroll
            for (int kk = 0; kk < 4; kk++) {
                int off = (nt * 8 + g) * 144 + (kk * 16 + 2 * tig) * 2;
                unsigned bh[2], bl[2];
                bh[0] = *(const unsigned*)(sKh + off);
                bh[1] = *(const unsigned*)(sKh + off + 16);
                bl[0] = *(const unsigned*)(sKl + off);
                bl[1] = *(const unsigned*)(sKl + off + 16);
                mma_bf16(sc[nt], qh[kk], bh);
                mma_bf16(sc[nt], qh[kk], bl);
                mma_bf16(sc[nt], ql[kk], bh);
            }
        }

        float mxa = -CUDART_INF_F, mxb = -CUDART_INF_F;
        #pragma unroll
        for (int nt = 0; nt < 8; nt++) {
            int jc = j0 + nt * 8 + 2 * tig;
            if (jc     > ra) sc[nt][0] = -CUDART_INF_F;
            if (jc + 1 > ra) sc[nt][1] = -CUDART_INF_F;
            if (jc     > rb) sc[nt][2] = -CUDART_INF_F;
            if (jc + 1 > rb) sc[nt][3] = -CUDART_INF_F;
            mxa = fmaxf(mxa, fmaxf(sc[nt][0], sc[nt][1]));
            mxb = fmaxf(mxb, fmaxf(sc[nt][2], sc[nt][3]));
        }
        mxa = fmaxf(mxa, __shfl_xor_sync(0xffffffffu, mxa, 1));
        mxa = fmaxf(mxa, __shfl_xor_sync(0xffffffffu, mxa, 2));
        mxb = fmaxf(mxb, __shfl_xor_sync(0xffffffffu, mxb, 1));
        mxb = fmaxf(mxb, __shfl_xor_sync(0xffffffffu, mxb, 2));

        float mna = fmaxf(m_a, mxa), mnb = fmaxf(m_b, mxb);
        float alpha_a = exp2f((m_a - mna) * SCV);
        float alpha_b = exp2f((m_b - mnb) * SCV);
        m_a = mna; m_b = mnb;

        float p[8][4];
        float laa = 0.f, lba = 0.f;
        #pragma unroll
        for (int nt = 0; nt < 8; nt++) {
            p[nt][0] = exp2f((sc[nt][0] - mna) * SCV);
            p[nt][1] = exp2f((sc[nt][1] - mna) * SCV);
            p[nt][2] = exp2f((sc[nt][2] - mnb) * SCV);
            p[nt][3] = exp2f((sc[nt][3] - mnb) * SCV);
            laa += p[nt][0] + p[nt][1];
            lba += p[nt][2] + p[nt][3];
        }
        laa += __shfl_xor_sync(0xffffffffu, laa, 1);
        laa += __shfl_xor_sync(0xffffffffu, laa, 2);
        lba += __shfl_xor_sync(0xffffffffu, lba, 1);
        lba += __shfl_xor_sync(0xffffffffu, lba, 2);
        l_a = l_a * alpha_a + laa;
        l_b = l_b * alpha_b + lba;

        #pragma unroll
        for (int nt = 0; nt < 8; nt++) {
            o[nt][0] *= alpha_a; o[nt][1] *= alpha_a;
            o[nt][2] *= alpha_b; o[nt][3] *= alpha_b;
        }

        unsigned ph[4][4], pl[4][4];
        #pragma unroll
        for (int k2 = 0; k2 < 4; k2++) {
            int n0 = 2 * k2, n1 = 2 * k2 + 1;
            #pragma unroll
            for (int e = 0; e < 4; e++) {
                int nt = (e < 2) ? n0 : n1;
                int e0 = (e & 1) ? 2 : 0;
                float pa = p[nt][e0], pb = p[nt][e0 + 1];
                unsigned hp = pk_bf2(pa, pb);
                float ha = __uint_as_float(hp << 16);
                float hb = __uint_as_float(hp & 0xffff0000u);
                ph[k2][e] = hp;
                pl[k2][e] = pk_bf2(pa - ha, pb - hb);
            }
        }

        #pragma unroll
        for (int nt = 0; nt < 8; nt++) {
            #pragma unroll
            for (int k2 = 0; k2 < 4; k2++) {
                int off = (nt * 8 + g) * 144 + (k2 * 16 + 2 * tig) * 2;
                unsigned vh[2], vl[2];
                vh[0] = *(const unsigned*)(sVh + off);
                vh[1] = *(const unsigned*)(sVh + off + 16);
                vl[0] = *(const unsigned*)(sVl + off);
                vl[1] = *(const unsigned*)(sVl + off + 16);
                mma_bf16(o[nt], ph[k2], vh);
                mma_bf16(o[nt], ph[k2], vl);
                mma_bf16(o[nt], pl[k2], vh);
            }
        }
    }

    size_t pa_off = ((size_t)ks * ROWS + bT + ra) * HS;
    size_t pb_off = ((size_t)ks * ROWS + bT + rb) * HS;
    #pragma unroll
    for (int nt = 0; nt < 8; nt++) {
        *(float2*)&g_po[pa_off + nt * 8 + 2 * tig] = make_float2(o[nt][0], o[nt][1]);
        *(float2*)&g_po[pb_off + nt * 8 + 2 * tig] = make_float2(o[nt][2], o[nt][3]);
    }
    if (tig == 0) {
        g_pm[ks * ROWS + bT + ra] = m_a * 8.0f;
        g_pl[ks * ROWS + bT + ra] = l_a;
        g_pm[ks * ROWS + bT + rb] = m_b * 8.0f;
        g_pl[ks * ROWS + bT + rb] = l_b;
    }
}

/* ---------------- combine split partials -------------------------------- */
__global__ __launch_bounds__(256)
void attn_combine_kernel(float* __restrict__ out) {
    int t = blockIdx.x * blockDim.x + threadIdx.x;
    if (t >= ROWS * 16) return;
    int row = t >> 4;
    int d4  = t & 15;
    int smax = (row & (TT - 1)) >> 7;

    float m = -CUDART_INF_F;
    for (int s = 0; s <= smax; s++) m = fmaxf(m, g_pm[s * ROWS + row]);

    float l = 0.f;
    float4 acc = make_float4(0.f, 0.f, 0.f, 0.f);
    for (int s = 0; s <= smax; s++) {
        float wgt = __expf(g_pm[s * ROWS + row] - m);
        l += g_pl[s * ROWS + row] * wgt;
        float4 p = ((const float4*)g_po)[((size_t)s * ROWS + row) * 16 + d4];
        acc.x = fmaf(wgt, p.x, acc.x);
        acc.y = fmaf(wgt, p.y, acc.y);
        acc.z = fmaf(wgt, p.z, acc.z);
        acc.w = fmaf(wgt, p.w, acc.w);
    }
    float inv = 1.f / l;
    ((float4*)out)[(size_t)row * 16 + d4] =
        make_float4(acc.x * inv, acc.y * inv, acc.z * inv, acc.w * inv);
}

/* ---------------- launch ------------------------------------------------ */
extern "C" void kernel_launch(void* const* d_in, const int* in_sizes, int n_in,
                              void* d_out, int out_size) {
    (void)in_sizes; (void)n_in; (void)out_size;
    const float* x  = (const float*)d_in[0];
    const float* Wq = (const float*)d_in[1];
    const float* bq = (const float*)d_in[2];
    const float* Wk = (const float*)d_in[3];
    const float* bk = (const float*)d_in[4];
    const float* Wv = (const float*)d_in[5];

    build_b_kernel<<<NCOL * DM / 256, 256>>>(Wq, Wk, Wv);
    qkv_mma_kernel<<<dim3(ROWS / 128, 3), 256>>>(x, bq, bk);
    attn_mma_kernel<<<dim3(TRI, BB), 256>>>();
    attn_combine_kernel<<<(ROWS * 16 + 255) / 256, 256>>>((float*)d_out);
}

// round 8
// speedup vs baseline: 3.2586x; 1.0875x over previous
#include <cuda_runtime.h>
#include <cuda_bf16.h>
#include <math_constants.h>
#include <cstdint>

#define DM   1024
#define HS   64
#define BB   4
#define TT   2048
#define ROWS (BB * TT)        /* 8192 */
#define NS   8                /* key splits (SPLIT = 256) */
#define SPLIT 256
#define TRI2 72               /* sum ceil((qt+1)/2), qt=0..15 */
#define NCOL 192              /* q|k|v fused output columns */
#define SCV  11.541560327111707f   /* 8 * log2(e) */

typedef unsigned long long u64;

/* ---------------- helpers ------------------------------------------------ */
__device__ __forceinline__ unsigned pk_bf2(float a, float b) {  /* lo=a, hi=b */
    unsigned r;
    asm("cvt.rn.bf16x2.f32 %0, %1, %2;" : "=r"(r) : "f"(b), "f"(a));
    return r;
}
__device__ __forceinline__ void mma_bf16(float* d, const unsigned* a, const unsigned* b) {
    asm volatile(
        "mma.sync.aligned.m16n8k16.row.col.f32.bf16.bf16.f32 "
        "{%0,%1,%2,%3}, {%4,%5,%6,%7}, {%8,%9}, {%0,%1,%2,%3};"
        : "+f"(d[0]), "+f"(d[1]), "+f"(d[2]), "+f"(d[3])
        : "r"(a[0]), "r"(a[1]), "r"(a[2]), "r"(a[3]), "r"(b[0]), "r"(b[1]));
}
/* split float4 -> packed bf16 hi u64 + lo u64 */
__device__ __forceinline__ void split4(float4 v, u64& hi, u64& lo) {
    unsigned h01 = pk_bf2(v.x, v.y), h23 = pk_bf2(v.z, v.w);
    float h0 = __uint_as_float(h01 << 16);
    float h1 = __uint_as_float(h01 & 0xffff0000u);
    float h2 = __uint_as_float(h23 << 16);
    float h3 = __uint_as_float(h23 & 0xffff0000u);
    unsigned l01 = pk_bf2(v.x - h0, v.y - h1), l23 = pk_bf2(v.z - h2, v.w - h3);
    hi = ((u64)h23 << 32) | h01;
    lo = ((u64)l23 << 32) | l01;
}

/* ---------------- device scratch ---------------------------------------- */
__device__ u64 g_Bh[NCOL * DM / 4];          /* W^T fused [192][1024] hi */
__device__ u64 g_Bl[NCOL * DM / 4];
__device__ uint16_t g_qh[ROWS * HS], g_ql[ROWS * HS];   /* bf16 hi/lo */
__device__ uint16_t g_kh[ROWS * HS], g_kl[ROWS * HS];
__device__ uint16_t g_vth[BB * HS * TT], g_vtl[BB * HS * TT];  /* V^T [b][d][t] */
__device__ float g_po[(size_t)NS * ROWS * HS];
__device__ float g_pm[NS * ROWS];
__device__ float g_pl[NS * ROWS];

/* ---------------- build fused transposed weight B[n][k] ------------------ */
__global__ __launch_bounds__(256)
void build_b_kernel(const float* __restrict__ Wq, const float* __restrict__ Wk,
                    const float* __restrict__ Wv) {
    int i = blockIdx.x * 256 + threadIdx.x;           /* n*1024 + k */
    int n = i >> 10, k = i & 1023;
    const float* W = (n < 64) ? Wq : ((n < 128) ? Wk : Wv);
    float v = W[(size_t)k * HS + (n & 63)];
    unsigned hp = pk_bf2(v, 0.f);
    float h = __uint_as_float(hp << 16);
    unsigned lp = pk_bf2(v - h, 0.f);
    ((uint16_t*)g_Bh)[i] = (uint16_t)(hp & 0xffffu);
    ((uint16_t*)g_Bl)[i] = (uint16_t)(lp & 0xffffu);
}

/* ---------------- QKV GEMM via mma.sync bf16 (hi/lo split) -------------- */
#define APITCH 80
#define TPITCH 132
__global__ __launch_bounds__(256)
void qkv_mma_kernel(const float* __restrict__ x,
                    const float* __restrict__ bq, const float* __restrict__ bk) {
    /* union: main loop tiles (30720 B)  |  V epilogue transpose (33792 B) */
    __shared__ __align__(16) uint8_t sbuf[64 * TPITCH * 4];
    uint8_t* sAh = sbuf;                       /* 128*80 = 10240 */
    uint8_t* sAl = sbuf + 10240;               /* 10240 */
    uint8_t* sBh = sbuf + 20480;               /* 64*80 = 5120 */
    uint8_t* sBl = sbuf + 25600;               /* 5120  */
    float*   sT  = (float*)sbuf;               /* 64 x TPITCH fp32 */

    const int tid   = threadIdx.x;
    const int which = blockIdx.y;
    const int row0  = blockIdx.x * 128;
    const int w     = tid >> 5;
    const int lane  = tid & 31;
    const int wm    = w & 3;
    const int wn    = w >> 2;
    const int g     = lane >> 2;
    const int tig   = lane & 3;

    int ar[4], aj[4], br[2], bj[2];
    #pragma unroll
    for (int t = 0; t < 4; t++) { int i = tid + t * 256; ar[t] = i >> 3; aj[t] = i & 7; }
    #pragma unroll
    for (int t = 0; t < 2; t++) { int i = tid + t * 256; br[t] = i >> 3; bj[t] = i & 7; }

    float acc[2][4][4];
    #pragma unroll
    for (int mt = 0; mt < 2; mt++)
        #pragma unroll
        for (int nt = 0; nt < 4; nt++)
            #pragma unroll
            for (int e = 0; e < 4; e++) acc[mt][nt][e] = 0.f;

    float4 fa[4];
    u64 rbh[2], rbl[2];
    #pragma unroll
    for (int t = 0; t < 4; t++)
        fa[t] = *(const float4*)(x + (size_t)(row0 + ar[t]) * DM + aj[t] * 4);
    #pragma unroll
    for (int t = 0; t < 2; t++) {
        size_t o = (size_t)(which * 64 + br[t]) * 256 + bj[t];
        rbh[t] = g_Bh[o]; rbl[t] = g_Bl[o];
    }

    for (int c = 0; c < 32; c++) {
        #pragma unroll
        for (int t = 0; t < 4; t++) {
            u64 hi, lo;
            split4(fa[t], hi, lo);
            *(u64*)(sAh + ar[t] * APITCH + aj[t] * 8) = hi;
            *(u64*)(sAl + ar[t] * APITCH + aj[t] * 8) = lo;
        }
        #pragma unroll
        for (int t = 0; t < 2; t++) {
            *(u64*)(sBh + br[t] * APITCH + bj[t] * 8) = rbh[t];
            *(u64*)(sBl + br[t] * APITCH + bj[t] * 8) = rbl[t];
        }
        __syncthreads();

        if (c + 1 < 32) {
            #pragma unroll
            for (int t = 0; t < 4; t++)
                fa[t] = *(const float4*)(x + (size_t)(row0 + ar[t]) * DM
                                           + (c + 1) * 32 + aj[t] * 4);
            #pragma unroll
            for (int t = 0; t < 2; t++) {
                size_t o = (size_t)(which * 64 + br[t]) * 256 + (c + 1) * 8 + bj[t];
                rbh[t] = g_Bh[o]; rbl[t] = g_Bl[o];
            }
        }

        #pragma unroll
        for (int ks = 0; ks < 2; ks++) {
            unsigned ah[2][4], al[2][4], bh[4][2], bl[4][2];
            #pragma unroll
            for (int mt = 0; mt < 2; mt++) {
                int base = (wm * 32 + mt * 16 + g) * APITCH + ks * 32 + tig * 4;
                ah[mt][0] = *(const unsigned*)(sAh + base);
                ah[mt][1] = *(const unsigned*)(sAh + base + 8 * APITCH);
                ah[mt][2] = *(const unsigned*)(sAh + base + 16);
                ah[mt][3] = *(const unsigned*)(sAh + base + 8 * APITCH + 16);
                al[mt][0] = *(const unsigned*)(sAl + base);
                al[mt][1] = *(const unsigned*)(sAl + base + 8 * APITCH);
                al[mt][2] = *(const unsigned*)(sAl + base + 16);
                al[mt][3] = *(const unsigned*)(sAl + base + 8 * APITCH + 16);
            }
            #pragma unroll
            for (int nt = 0; nt < 4; nt++) {
                int base = (wn * 32 + nt * 8 + g) * APITCH + ks * 32 + tig * 4;
                bh[nt][0] = *(const unsigned*)(sBh + base);
                bh[nt][1] = *(const unsigned*)(sBh + base + 16);
                bl[nt][0] = *(const unsigned*)(sBl + base);
                bl[nt][1] = *(const unsigned*)(sBl + base + 16);
            }
            #pragma unroll
            for (int mt = 0; mt < 2; mt++)
                #pragma unroll
                for (int nt = 0; nt < 4; nt++) {
                    mma_bf16(acc[mt][nt], ah[mt], bh[nt]);
                    mma_bf16(acc[mt][nt], ah[mt], bl[nt]);
                    mma_bf16(acc[mt][nt], al[mt], bh[nt]);
                }
        }
        __syncthreads();
    }

    if (which < 2) {
        uint16_t* dh = (which == 0) ? g_qh : g_kh;
        uint16_t* dl = (which == 0) ? g_ql : g_kl;
        const float* bias = (which == 0) ? bq : bk;
        #pragma unroll
        for (int mt = 0; mt < 2; mt++) {
            #pragma unroll
            for (int nt = 0; nt < 4; nt++) {
                int m = row0 + wm * 32 + mt * 16 + g;
                int n = wn * 32 + nt * 8 + tig * 2;
                float bx = bias[n], by = bias[n + 1];
                float v0x = acc[mt][nt][0] + bx, v0y = acc[mt][nt][1] + by;
                float v1x = acc[mt][nt][2] + bx, v1y = acc[mt][nt][3] + by;
                unsigned h0 = pk_bf2(v0x, v0y);
                unsigned h1 = pk_bf2(v1x, v1y);
                float h0x = __uint_as_float(h0 << 16);
                float h0y = __uint_as_float(h0 & 0xffff0000u);
                float h1x = __uint_as_float(h1 << 16);
                float h1y = __uint_as_float(h1 & 0xffff0000u);
                *(unsigned*)&dh[(size_t)m * HS + n]        = h0;
                *(unsigned*)&dl[(size_t)m * HS + n]        = pk_bf2(v0x - h0x, v0y - h0y);
                *(unsigned*)&dh[(size_t)(m + 8) * HS + n]  = h1;
                *(unsigned*)&dl[(size_t)(m + 8) * HS + n]  = pk_bf2(v1x - h1x, v1y - h1y);
            }
        }
    } else {
        /* V epilogue: transpose via smem, write V^T bf16 hi/lo coalesced */
        #pragma unroll
        for (int mt = 0; mt < 2; mt++) {
            #pragma unroll
            for (int nt = 0; nt < 4; nt++) {
                int ml = wm * 32 + mt * 16 + g;
                int n  = wn * 32 + nt * 8 + tig * 2;
                sT[n * TPITCH + ml]             = acc[mt][nt][0];
                sT[(n + 1) * TPITCH + ml]       = acc[mt][nt][1];
                sT[n * TPITCH + ml + 8]         = acc[mt][nt][2];
                sT[(n + 1) * TPITCH + ml + 8]   = acc[mt][nt][3];
            }
        }
        __syncthreads();
        const int b  = row0 >> 11;
        const int t0 = row0 & (TT - 1);
        #pragma unroll
        for (int t4 = 0; t4 < 8; t4++) {
            int idx = tid + t4 * 256;
            int d = idx >> 5, j = idx & 31;
            float4 v = *(const float4*)&sT[d * TPITCH + 4 * j];
            u64 hi, lo;
            split4(v, hi, lo);
            size_t o = ((size_t)(b * HS + d)) * TT + t0 + 4 * j;
            *(u64*)&g_vth[o] = hi;
            *(u64*)&g_vtl[o] = lo;
        }
    }
}

/* ---------------- causal flash-attention via mma.sync --------------------
 * SPLIT=256: block (qt, kb) handles keys [kb*256, kb*256+256) for q-tile qt.
 * Per-batch block count = sum ceil((qt+1)/2) = 72. 4 chunks of 64 keys. */
__global__ __launch_bounds__(256)
void attn_mma_kernel() {
    int t = blockIdx.x;            /* 0..71 */
    int b = blockIdx.y;
    int qt = 0, cum = 0;
    #pragma unroll
    for (int i = 0; i < 16; i++) {
        int cnt = (i + 2) >> 1;
        if (t < cum + cnt) { qt = i; break; }
        cum += cnt;
    }
    const int kb = t - cum;

    const int tid  = threadIdx.x;
    const int w    = tid >> 5;
    const int lane = tid & 31;
    const int g    = lane >> 2;
    const int tig  = lane & 3;
    const int r0   = qt * 128 + w * 16;
    const int bT   = b * TT;
    const int kend = qt * 128 + 128;      /* causal key limit for this tile */

    __shared__ __align__(16) uint8_t sKh[64 * 144];
    __shared__ __align__(16) uint8_t sKl[64 * 144];
    __shared__ __align__(16) uint8_t sVh[64 * 144];
    __shared__ __align__(16) uint8_t sVl[64 * 144];

    unsigned qh[4][4], ql[4][4];
    {
        const uint16_t* qah = g_qh + (size_t)(bT + r0 + g) * HS;
        const uint16_t* qal = g_ql + (size_t)(bT + r0 + g) * HS;
        #pragma unroll
        for (int kq = 0; kq < 4; kq++) {
            int c = kq * 16 + 2 * tig;
            qh[kq][0] = *(const unsigned*)(qah + c);
            qh[kq][1] = *(const unsigned*)(qah + 8 * HS + c);
            qh[kq][2] = *(const unsigned*)(qah + c + 8);
            qh[kq][3] = *(const unsigned*)(qah + 8 * HS + c + 8);
            ql[kq][0] = *(const unsigned*)(qal + c);
            ql[kq][1] = *(const unsigned*)(qal + 8 * HS + c);
            ql[kq][2] = *(const unsigned*)(qal + c + 8);
            ql[kq][3] = *(const unsigned*)(qal + 8 * HS + c + 8);
        }
    }

    float o[8][4];
    #pragma unroll
    for (int i = 0; i < 8; i++)
        #pragma unroll
        for (int e = 0; e < 4; e++) o[i][e] = 0.f;
    float m_a = -CUDART_INF_F, m_b = -CUDART_INF_F;
    float l_a = 0.f, l_b = 0.f;
    const int ra = r0 + g, rb = r0 + g + 8;

    for (int c2 = 0; c2 < 4; c2++) {
        const int j0 = kb * SPLIT + c2 * 64;
        if (j0 >= kend) break;             /* block-uniform causal cutoff */
        __syncthreads();
        #pragma unroll
        for (int t4 = 0; t4 < 4; t4++) {
            int i = tid + t4 * 256;
            int row = i >> 4, c8 = i & 15;
            *(u64*)(sKh + row * 144 + c8 * 8) =
                *(const u64*)(g_kh + (size_t)(bT + j0 + row) * HS + c8 * 4);
            *(u64*)(sKl + row * 144 + c8 * 8) =
                *(const u64*)(g_kl + (size_t)(bT + j0 + row) * HS + c8 * 4);
            *(u64*)(sVh + row * 144 + c8 * 8) =
                *(const u64*)(g_vth + (size_t)(b * HS + row) * TT + j0 + c8 * 4);
            *(u64*)(sVl + row * 144 + c8 * 8) =
                *(const u64*)(g_vtl + (size_t)(b * HS + row) * TT + j0 + c8 * 4);
        }
        __syncthreads();

        if (j0 > r0 + 15) continue;        /* warp-uniform skip */

        float sc[8][4];
        #pragma unroll
        for (int nt = 0; nt < 8; nt++)
            #pragma unroll
            for (int e = 0; e < 4; e++) sc[nt][e] = 0.f;

        #pragma unroll
        for (int nt = 0; nt < 8; nt++) {
            #pragma unroll
            for (int kk = 0; kk < 4; kk++) {
                int off = (nt * 8 + g) * 144 + (kk * 16 + 2 * tig) * 2;
                unsigned bh[2], bl[2];
                bh[0] = *(const unsigned*)(sKh + off);
                bh[1] = *(const unsigned*)(sKh + off + 16);
                bl[0] = *(const unsigned*)(sKl + off);
                bl[1] = *(const unsigned*)(sKl + off + 16);
                mma_bf16(sc[nt], qh[kk], bh);
                mma_bf16(sc[nt], qh[kk], bl);
                mma_bf16(sc[nt], ql[kk], bh);
            }
        }

        float mxa = -CUDART_INF_F, mxb = -CUDART_INF_F;
        #pragma unroll
        for (int nt = 0; nt < 8; nt++) {
            int jc = j0 + nt * 8 + 2 * tig;
            if (jc     > ra) sc[nt][0] = -CUDART_INF_F;
            if (jc + 1 > ra) sc[nt][1] = -CUDART_INF_F;
            if (jc     > rb) sc[nt][2] = -CUDART_INF_F;
            if (jc + 1 > rb) sc[nt][3] = -CUDART_INF_F;
            mxa = fmaxf(mxa, fmaxf(sc[nt][0], sc[nt][1]));
            mxb = fmaxf(mxb, fmaxf(sc[nt][2], sc[nt][3]));
        }
        mxa = fmaxf(mxa, __shfl_xor_sync(0xffffffffu, mxa, 1));
        mxa = fmaxf(mxa, __shfl_xor_sync(0xffffffffu, mxa, 2));
        mxb = fmaxf(mxb, __shfl_xor_sync(0xffffffffu, mxb, 1));
        mxb = fmaxf(mxb, __shfl_xor_sync(0xffffffffu, mxb, 2));

        float mna = fmaxf(m_a, mxa), mnb = fmaxf(m_b, mxb);
        float alpha_a = exp2f((m_a - mna) * SCV);
        float alpha_b = exp2f((m_b - mnb) * SCV);
        m_a = mna; m_b = mnb;

        float p[8][4];
        float laa = 0.f, lba = 0.f;
        #pragma unroll
        for (int nt = 0; nt < 8; nt++) {
            p[nt][0] = exp2f((sc[nt][0] - mna) * SCV);
            p[nt][1] = exp2f((sc[nt][1] - mna) * SCV);
            p[nt][2] = exp2f((sc[nt][2] - mnb) * SCV);
            p[nt][3] = exp2f((sc[nt][3] - mnb) * SCV);
            laa += p[nt][0] + p[nt][1];
            lba += p[nt][2] + p[nt][3];
        }
        laa += __shfl_xor_sync(0xffffffffu, laa, 1);
        laa += __shfl_xor_sync(0xffffffffu, laa, 2);
        lba += __shfl_xor_sync(0xffffffffu, lba, 1);
        lba += __shfl_xor_sync(0xffffffffu, lba, 2);
        l_a = l_a * alpha_a + laa;
        l_b = l_b * alpha_b + lba;

        #pragma unroll
        for (int nt = 0; nt < 8; nt++) {
            o[nt][0] *= alpha_a; o[nt][1] *= alpha_a;
            o[nt][2] *= alpha_b; o[nt][3] *= alpha_b;
        }

        unsigned ph[4][4], pl[4][4];
        #pragma unroll
        for (int k2 = 0; k2 < 4; k2++) {
            int n0 = 2 * k2, n1 = 2 * k2 + 1;
            #pragma unroll
            for (int e = 0; e < 4; e++) {
                int nt = (e < 2) ? n0 : n1;
                int e0 = (e & 1) ? 2 : 0;
                float pa = p[nt][e0], pb = p[nt][e0 + 1];
                unsigned hp = pk_bf2(pa, pb);
                float ha = __uint_as_float(hp << 16);
                float hb = __uint_as_float(hp & 0xffff0000u);
                ph[k2][e] = hp;
                pl[k2][e] = pk_bf2(pa - ha, pb - hb);
            }
        }

        #pragma unroll
        for (int nt = 0; nt < 8; nt++) {
            #pragma unroll
            for (int k2 = 0; k2 < 4; k2++) {
                int off = (nt * 8 + g) * 144 + (k2 * 16 + 2 * tig) * 2;
                unsigned vh[2], vl[2];
                vh[0] = *(const unsigned*)(sVh + off);
                vh[1] = *(const unsigned*)(sVh + off + 16);
                vl[0] = *(const unsigned*)(sVl + off);
                vl[1] = *(const unsigned*)(sVl + off + 16);
                mma_bf16(o[nt], ph[k2], vh);
                mma_bf16(o[nt], ph[k2], vl);
                mma_bf16(o[nt], pl[k2], vh);
            }
        }
    }

    size_t pa_off = ((size_t)kb * ROWS + bT + ra) * HS;
    size_t pb_off = ((size_t)kb * ROWS + bT + rb) * HS;
    #pragma unroll
    for (int nt = 0; nt < 8; nt++) {
        *(float2*)&g_po[pa_off + nt * 8 + 2 * tig] = make_float2(o[nt][0], o[nt][1]);
        *(float2*)&g_po[pb_off + nt * 8 + 2 * tig] = make_float2(o[nt][2], o[nt][3]);
    }
    if (tig == 0) {
        g_pm[kb * ROWS + bT + ra] = m_a * 8.0f;
        g_pl[kb * ROWS + bT + ra] = l_a;
        g_pm[kb * ROWS + bT + rb] = m_b * 8.0f;
        g_pl[kb * ROWS + bT + rb] = l_b;
    }
}

/* ---------------- combine split partials (high-ILP) ---------------------- */
__global__ __launch_bounds__(256)
void attn_combine_kernel(float* __restrict__ out) {
    int t = blockIdx.x * blockDim.x + threadIdx.x;
    if (t >= ROWS * 16) return;
    int row = t >> 4;
    int d4  = t & 15;
    int smax = (row & (TT - 1)) >> 8;      /* active splits: 0..smax, <= 7 */

    float mm[NS], ll[NS];
    #pragma unroll
    for (int s = 0; s < NS; s++) {
        bool a = (s <= smax);
        mm[s] = a ? g_pm[s * ROWS + row] : -CUDART_INF_F;
        ll[s] = a ? g_pl[s * ROWS + row] : 0.f;
    }
    float4 po[NS];
    #pragma unroll
    for (int s = 0; s < NS; s++) {
        po[s] = (s <= smax)
              ? ((const float4*)g_po)[((size_t)s * ROWS + row) * 16 + d4]
              : make_float4(0.f, 0.f, 0.f, 0.f);
    }

    float m = -CUDART_INF_F;
    #pragma unroll
    for (int s = 0; s < NS; s++) m = fmaxf(m, mm[s]);

    float l = 0.f;
    float4 acc = make_float4(0.f, 0.f, 0.f, 0.f);
    #pragma unroll
    for (int s = 0; s < NS; s++) {
        float wgt = __expf(mm[s] - m);     /* -inf -> 0 */
        l += ll[s] * wgt;
        acc.x = fmaf(wgt, po[s].x, acc.x);
        acc.y = fmaf(wgt, po[s].y, acc.y);
        acc.z = fmaf(wgt, po[s].z, acc.z);
        acc.w = fmaf(wgt, po[s].w, acc.w);
    }
    float inv = 1.f / l;
    ((float4*)out)[(size_t)row * 16 + d4] =
        make_float4(acc.x * inv, acc.y * inv, acc.z * inv, acc.w * inv);
}

/* ---------------- launch ------------------------------------------------ */
extern "C" void kernel_launch(void* const* d_in, const int* in_sizes, int n_in,
                              void* d_out, int out_size) {
    (void)in_sizes; (void)n_in; (void)out_size;
    const float* x  = (const float*)d_in[0];
    const float* Wq = (const float*)d_in[1];
    const float* bq = (const float*)d_in[2];
    const float* Wk = (const float*)d_in[3];
    const float* bk = (const float*)d_in[4];
    const float* Wv = (const float*)d_in[5];

    build_b_kernel<<<NCOL * DM / 256, 256>>>(Wq, Wk, Wv);
    qkv_mma_kernel<<<dim3(ROWS / 128, 3), 256>>>(x, bq, bk);
    attn_mma_kernel<<<dim3(TRI2, BB), 256>>>();
    attn_combine_kernel<<<(ROWS * 16 + 255) / 256, 256>>>((float*)d_out);
}

// round 9
// speedup vs baseline: 3.7332x; 1.1456x over previous
#include <cuda_runtime.h>
#include <cuda_bf16.h>
#include <math_constants.h>
#include <cstdint>

#define DM   1024
#define HS   64
#define BB   4
#define TT   2048
#define ROWS (BB * TT)        /* 8192 */
#define NS   8                /* key splits (SPLIT = 256) */
#define SPLIT 256
#define TRI2 72               /* sum ceil((qt+1)/2), qt=0..15 */
#define NCOL 192              /* q|k|v fused output columns */
#define SCV  11.541560327111707f   /* 8 * log2(e) */

typedef unsigned long long u64;

/* ---------------- helpers ------------------------------------------------ */
__device__ __forceinline__ unsigned pk_bf2(float a, float b) {  /* lo=a, hi=b */
    unsigned r;
    asm("cvt.rn.bf16x2.f32 %0, %1, %2;" : "=r"(r) : "f"(b), "f"(a));
    return r;
}
__device__ __forceinline__ void mma_bf16(float* d, const unsigned* a, const unsigned* b) {
    asm volatile(
        "mma.sync.aligned.m16n8k16.row.col.f32.bf16.bf16.f32 "
        "{%0,%1,%2,%3}, {%4,%5,%6,%7}, {%8,%9}, {%0,%1,%2,%3};"
        : "+f"(d[0]), "+f"(d[1]), "+f"(d[2]), "+f"(d[3])
        : "r"(a[0]), "r"(a[1]), "r"(a[2]), "r"(a[3]), "r"(b[0]), "r"(b[1]));
}
__device__ __forceinline__ void ldsm_x4(unsigned* r, uint32_t addr) {
    asm volatile("ldmatrix.sync.aligned.m8n8.x4.shared.b16 {%0,%1,%2,%3}, [%4];"
        : "=r"(r[0]), "=r"(r[1]), "=r"(r[2]), "=r"(r[3]) : "r"(addr));
}
__device__ __forceinline__ uint32_t smem_u32(const void* p) {
    uint32_t a;
    asm("{ .reg .u64 t; cvta.to.shared.u64 t, %1; cvt.u32.u64 %0, t; }"
        : "=r"(a) : "l"(p));
    return a;
}
/* split float4 -> packed bf16 hi u64 + lo u64 */
__device__ __forceinline__ void split4(float4 v, u64& hi, u64& lo) {
    unsigned h01 = pk_bf2(v.x, v.y), h23 = pk_bf2(v.z, v.w);
    float h0 = __uint_as_float(h01 << 16);
    float h1 = __uint_as_float(h01 & 0xffff0000u);
    float h2 = __uint_as_float(h23 << 16);
    float h3 = __uint_as_float(h23 & 0xffff0000u);
    unsigned l01 = pk_bf2(v.x - h0, v.y - h1), l23 = pk_bf2(v.z - h2, v.w - h3);
    hi = ((u64)h23 << 32) | h01;
    lo = ((u64)l23 << 32) | l01;
}

/* ---------------- device scratch ---------------------------------------- */
__device__ u64 g_Bh[NCOL * DM / 4];          /* W^T fused [192][1024] hi */
__device__ u64 g_Bl[NCOL * DM / 4];
__device__ uint16_t g_qh[ROWS * HS], g_ql[ROWS * HS];   /* bf16 hi/lo */
__device__ uint16_t g_kh[ROWS * HS], g_kl[ROWS * HS];
__device__ uint16_t g_vth[BB * HS * TT], g_vtl[BB * HS * TT];  /* V^T [b][d][t] */
__device__ float g_po[(size_t)NS * ROWS * HS];
__device__ float g_pm[NS * ROWS];
__device__ float g_pl[NS * ROWS];

/* ---------------- build fused transposed weight B[n][k] ------------------ */
__global__ __launch_bounds__(256)
void build_b_kernel(const float* __restrict__ Wq, const float* __restrict__ Wk,
                    const float* __restrict__ Wv) {
    int i = blockIdx.x * 256 + threadIdx.x;           /* n*1024 + k */
    int n = i >> 10, k = i & 1023;
    const float* W = (n < 64) ? Wq : ((n < 128) ? Wk : Wv);
    float v = W[(size_t)k * HS + (n & 63)];
    unsigned hp = pk_bf2(v, 0.f);
    float h = __uint_as_float(hp << 16);
    unsigned lp = pk_bf2(v - h, 0.f);
    ((uint16_t*)g_Bh)[i] = (uint16_t)(hp & 0xffffu);
    ((uint16_t*)g_Bl)[i] = (uint16_t)(lp & 0xffffu);
}

/* ---------------- QKV GEMM via mma.sync bf16 (hi/lo split, ldmatrix) ---- */
#define APITCH 80
#define TPITCH 132
__global__ __launch_bounds__(256)
void qkv_mma_kernel(const float* __restrict__ x,
                    const float* __restrict__ bq, const float* __restrict__ bk) {
    /* union: main loop tiles (30720 B)  |  V epilogue transpose (33792 B) */
    __shared__ __align__(128) uint8_t sbuf[64 * TPITCH * 4];
    uint8_t* sAh = sbuf;                       /* 128*80 = 10240 */
    uint8_t* sAl = sbuf + 10240;               /* 10240 */
    uint8_t* sBh = sbuf + 20480;               /* 64*80 = 5120 */
    uint8_t* sBl = sbuf + 25600;               /* 5120  */
    float*   sT  = (float*)sbuf;               /* 64 x TPITCH fp32 */

    const int tid   = threadIdx.x;
    const int which = blockIdx.y;
    const int row0  = blockIdx.x * 128;
    const int w     = tid >> 5;
    const int lane  = tid & 31;
    const int wm    = w & 3;
    const int wn    = w >> 2;
    const int g     = lane >> 2;
    const int tig   = lane & 3;

    const uint32_t aBh = smem_u32(sAh), aBl = smem_u32(sAl);
    const uint32_t bBh = smem_u32(sBh), bBl = smem_u32(sBl);
    /* ldmatrix lane-address components */
    const int l7  = lane & 7;
    const int q01 = (lane >> 3) & 1;
    const int q2  = lane >> 4;

    int ar[4], aj[4], br[2], bj[2];
    #pragma unroll
    for (int t = 0; t < 4; t++) { int i = tid + t * 256; ar[t] = i >> 3; aj[t] = i & 7; }
    #pragma unroll
    for (int t = 0; t < 2; t++) { int i = tid + t * 256; br[t] = i >> 3; bj[t] = i & 7; }

    float acc[2][4][4];
    #pragma unroll
    for (int mt = 0; mt < 2; mt++)
        #pragma unroll
        for (int nt = 0; nt < 4; nt++)
            #pragma unroll
            for (int e = 0; e < 4; e++) acc[mt][nt][e] = 0.f;

    float4 fa[4];
    u64 rbh[2], rbl[2];
    #pragma unroll
    for (int t = 0; t < 4; t++)
        fa[t] = *(const float4*)(x + (size_t)(row0 + ar[t]) * DM + aj[t] * 4);
    #pragma unroll
    for (int t = 0; t < 2; t++) {
        size_t o = (size_t)(which * 64 + br[t]) * 256 + bj[t];
        rbh[t] = g_Bh[o]; rbl[t] = g_Bl[o];
    }

    for (int c = 0; c < 32; c++) {
        #pragma unroll
        for (int t = 0; t < 4; t++) {
            u64 hi, lo;
            split4(fa[t], hi, lo);
            *(u64*)(sAh + ar[t] * APITCH + aj[t] * 8) = hi;
            *(u64*)(sAl + ar[t] * APITCH + aj[t] * 8) = lo;
        }
        #pragma unroll
        for (int t = 0; t < 2; t++) {
            *(u64*)(sBh + br[t] * APITCH + bj[t] * 8) = rbh[t];
            *(u64*)(sBl + br[t] * APITCH + bj[t] * 8) = rbl[t];
        }
        __syncthreads();

        if (c + 1 < 32) {
            #pragma unroll
            for (int t = 0; t < 4; t++)
                fa[t] = *(const float4*)(x + (size_t)(row0 + ar[t]) * DM
                                           + (c + 1) * 32 + aj[t] * 4);
            #pragma unroll
            for (int t = 0; t < 2; t++) {
                size_t o = (size_t)(which * 64 + br[t]) * 256 + (c + 1) * 8 + bj[t];
                rbh[t] = g_Bh[o]; rbl[t] = g_Bl[o];
            }
        }

        #pragma unroll
        for (int ks = 0; ks < 2; ks++) {
            unsigned ah[2][4], al[2][4], bhv[2][4], blv[2][4];
            #pragma unroll
            for (int mt = 0; mt < 2; mt++) {
                uint32_t aoff = (uint32_t)((wm * 32 + mt * 16 + q01 * 8 + l7) * APITCH
                                           + ks * 32 + q2 * 16);
                ldsm_x4(ah[mt], aBh + aoff);
                ldsm_x4(al[mt], aBl + aoff);
            }
            #pragma unroll
            for (int p = 0; p < 2; p++) {
                uint32_t boff = (uint32_t)((wn * 32 + p * 16 + q2 * 8 + l7) * APITCH
                                           + ks * 32 + q01 * 16);
                ldsm_x4(bhv[p], bBh + boff);
                ldsm_x4(blv[p], bBl + boff);
            }
            #pragma unroll
            for (int mt = 0; mt < 2; mt++)
                #pragma unroll
                for (int nt = 0; nt < 4; nt++) {
                    const unsigned* bh = &bhv[nt >> 1][(nt & 1) * 2];
                    const unsigned* bl = &blv[nt >> 1][(nt & 1) * 2];
                    mma_bf16(acc[mt][nt], ah[mt], bh);
                    mma_bf16(acc[mt][nt], ah[mt], bl);
                    mma_bf16(acc[mt][nt], al[mt], bh);
                }
        }
        __syncthreads();
    }

    if (which < 2) {
        uint16_t* dh = (which == 0) ? g_qh : g_kh;
        uint16_t* dl = (which == 0) ? g_ql : g_kl;
        const float* bias = (which == 0) ? bq : bk;
        #pragma unroll
        for (int mt = 0; mt < 2; mt++) {
            #pragma unroll
            for (int nt = 0; nt < 4; nt++) {
                int m = row0 + wm * 32 + mt * 16 + g;
                int n = wn * 32 + nt * 8 + tig * 2;
                float bx = bias[n], by = bias[n + 1];
                float v0x = acc[mt][nt][0] + bx, v0y = acc[mt][nt][1] + by;
                float v1x = acc[mt][nt][2] + bx, v1y = acc[mt][nt][3] + by;
                unsigned h0 = pk_bf2(v0x, v0y);
                unsigned h1 = pk_bf2(v1x, v1y);
                float h0x = __uint_as_float(h0 << 16);
                float h0y = __uint_as_float(h0 & 0xffff0000u);
                float h1x = __uint_as_float(h1 << 16);
                float h1y = __uint_as_float(h1 & 0xffff0000u);
                *(unsigned*)&dh[(size_t)m * HS + n]        = h0;
                *(unsigned*)&dl[(size_t)m * HS + n]        = pk_bf2(v0x - h0x, v0y - h0y);
                *(unsigned*)&dh[(size_t)(m + 8) * HS + n]  = h1;
                *(unsigned*)&dl[(size_t)(m + 8) * HS + n]  = pk_bf2(v1x - h1x, v1y - h1y);
            }
        }
    } else {
        /* V epilogue: transpose via smem, write V^T bf16 hi/lo coalesced */
        #pragma unroll
        for (int mt = 0; mt < 2; mt++) {
            #pragma unroll
            for (int nt = 0; nt < 4; nt++) {
                int ml = wm * 32 + mt * 16 + g;
                int n  = wn * 32 + nt * 8 + tig * 2;
                sT[n * TPITCH + ml]             = acc[mt][nt][0];
                sT[(n + 1) * TPITCH + ml]       = acc[mt][nt][1];
                sT[n * TPITCH + ml + 8]         = acc[mt][nt][2];
                sT[(n + 1) * TPITCH + ml + 8]   = acc[mt][nt][3];
            }
        }
        __syncthreads();
        const int b  = row0 >> 11;
        const int t0 = row0 & (TT - 1);
        #pragma unroll
        for (int t4 = 0; t4 < 8; t4++) {
            int idx = tid + t4 * 256;
            int d = idx >> 5, j = idx & 31;
            float4 v = *(const float4*)&sT[d * TPITCH + 4 * j];
            u64 hi, lo;
            split4(v, hi, lo);
            size_t o = ((size_t)(b * HS + d)) * TT + t0 + 4 * j;
            *(u64*)&g_vth[o] = hi;
            *(u64*)&g_vtl[o] = lo;
        }
    }
}

/* ---------------- causal flash-attention via mma.sync + ldmatrix -------- */
__global__ __launch_bounds__(256)
void attn_mma_kernel() {
    int t = blockIdx.x;            /* 0..71 */
    int b = blockIdx.y;
    int qt = 0, cum = 0;
    #pragma unroll
    for (int i = 0; i < 16; i++) {
        int cnt = (i + 2) >> 1;
        if (t < cum + cnt) { qt = i; break; }
        cum += cnt;
    }
    const int kb = t - cum;

    const int tid  = threadIdx.x;
    const int w    = tid >> 5;
    const int lane = tid & 31;
    const int g    = lane >> 2;
    const int tig  = lane & 3;
    const int r0   = qt * 128 + w * 16;
    const int bT   = b * TT;
    const int kend = qt * 128 + 128;      /* causal key limit for this tile */

    __shared__ __align__(128) uint8_t sKh[64 * 144];
    __shared__ __align__(128) uint8_t sKl[64 * 144];
    __shared__ __align__(128) uint8_t sVh[64 * 144];
    __shared__ __align__(128) uint8_t sVl[64 * 144];

    const uint32_t kBh = smem_u32(sKh), kBl = smem_u32(sKl);
    const uint32_t vBh = smem_u32(sVh), vBl = smem_u32(sVl);
    const int l7 = lane & 7;
    const int q4 = lane >> 3;            /* 0..3: k16-byte sub-offset */

    unsigned qh[4][4], ql[4][4];
    {
        const uint16_t* qah = g_qh + (size_t)(bT + r0 + g) * HS;
        const uint16_t* qal = g_ql + (size_t)(bT + r0 + g) * HS;
        #pragma unroll
        for (int kq = 0; kq < 4; kq++) {
            int c = kq * 16 + 2 * tig;
            qh[kq][0] = *(const unsigned*)(qah + c);
            qh[kq][1] = *(const unsigned*)(qah + 8 * HS + c);
            qh[kq][2] = *(const unsigned*)(qah + c + 8);
            qh[kq][3] = *(const unsigned*)(qah + 8 * HS + c + 8);
            ql[kq][0] = *(const unsigned*)(qal + c);
            ql[kq][1] = *(const unsigned*)(qal + 8 * HS + c);
            ql[kq][2] = *(const unsigned*)(qal + c + 8);
            ql[kq][3] = *(const unsigned*)(qal + 8 * HS + c + 8);
        }
    }

    float o[8][4];
    #pragma unroll
    for (int i = 0; i < 8; i++)
        #pragma unroll
        for (int e = 0; e < 4; e++) o[i][e] = 0.f;
    float m_a = -CUDART_INF_F, m_b = -CUDART_INF_F;
    float l_a = 0.f, l_b = 0.f;
    const int ra = r0 + g, rb = r0 + g + 8;

    for (int c2 = 0; c2 < 4; c2++) {
        const int j0 = kb * SPLIT + c2 * 64;
        if (j0 >= kend) break;             /* block-uniform causal cutoff */
        __syncthreads();
        #pragma unroll
        for (int t4 = 0; t4 < 4; t4++) {
            int i = tid + t4 * 256;
            int row = i >> 4, c8 = i & 15;
            *(u64*)(sKh + row * 144 + c8 * 8) =
                *(const u64*)(g_kh + (size_t)(bT + j0 + row) * HS + c8 * 4);
            *(u64*)(sKl + row * 144 + c8 * 8) =
                *(const u64*)(g_kl + (size_t)(bT + j0 + row) * HS + c8 * 4);
            *(u64*)(sVh + row * 144 + c8 * 8) =
                *(const u64*)(g_vth + (size_t)(b * HS + row) * TT + j0 + c8 * 4);
            *(u64*)(sVl + row * 144 + c8 * 8) =
                *(const u64*)(g_vtl + (size_t)(b * HS + row) * TT + j0 + c8 * 4);
        }
        __syncthreads();

        if (j0 > r0 + 15) continue;        /* warp-uniform skip */

        float sc[8][4];
        #pragma unroll
        for (int nt = 0; nt < 8; nt++)
            #pragma unroll
            for (int e = 0; e < 4; e++) sc[nt][e] = 0.f;

        #pragma unroll
        for (int nt = 0; nt < 8; nt++) {
            unsigned kh[8], kl[8];
            uint32_t rowoff = (uint32_t)((nt * 8 + l7) * 144 + q4 * 16);
            ldsm_x4(kh,     kBh + rowoff);
            ldsm_x4(kh + 4, kBh + rowoff + 64);
            ldsm_x4(kl,     kBl + rowoff);
            ldsm_x4(kl + 4, kBl + rowoff + 64);
            #pragma unroll
            for (int kk = 0; kk < 4; kk++) {
                mma_bf16(sc[nt], qh[kk], kh + kk * 2);
                mma_bf16(sc[nt], qh[kk], kl + kk * 2);
                mma_bf16(sc[nt], ql[kk], kh + kk * 2);
            }
        }

        float mxa = -CUDART_INF_F, mxb = -CUDART_INF_F;
        #pragma unroll
        for (int nt = 0; nt < 8; nt++) {
            int jc = j0 + nt * 8 + 2 * tig;
            if (jc     > ra) sc[nt][0] = -CUDART_INF_F;
            if (jc + 1 > ra) sc[nt][1] = -CUDART_INF_F;
            if (jc     > rb) sc[nt][2] = -CUDART_INF_F;
            if (jc + 1 > rb) sc[nt][3] = -CUDART_INF_F;
            mxa = fmaxf(mxa, fmaxf(sc[nt][0], sc[nt][1]));
            mxb = fmaxf(mxb, fmaxf(sc[nt][2], sc[nt][3]));
        }
        mxa = fmaxf(mxa, __shfl_xor_sync(0xffffffffu, mxa, 1));
        mxa = fmaxf(mxa, __shfl_xor_sync(0xffffffffu, mxa, 2));
        mxb = fmaxf(mxb, __shfl_xor_sync(0xffffffffu, mxb, 1));
        mxb = fmaxf(mxb, __shfl_xor_sync(0xffffffffu, mxb, 2));

        float mna = fmaxf(m_a, mxa), mnb = fmaxf(m_b, mxb);
        float alpha_a = exp2f((m_a - mna) * SCV);
        float alpha_b = exp2f((m_b - mnb) * SCV);
        m_a = mna; m_b = mnb;

        float p[8][4];
        float laa = 0.f, lba = 0.f;
        #pragma unroll
        for (int nt = 0; nt < 8; nt++) {
            p[nt][0] = exp2f((sc[nt][0] - mna) * SCV);
            p[nt][1] = exp2f((sc[nt][1] - mna) * SCV);
            p[nt][2] = exp2f((sc[nt][2] - mnb) * SCV);
            p[nt][3] = exp2f((sc[nt][3] - mnb) * SCV);
            laa += p[nt][0] + p[nt][1];
            lba += p[nt][2] + p[nt][3];
        }
        laa += __shfl_xor_sync(0xffffffffu, laa, 1);
        laa += __shfl_xor_sync(0xffffffffu, laa, 2);
        lba += __shfl_xor_sync(0xffffffffu, lba, 1);
        lba += __shfl_xor_sync(0xffffffffu, lba, 2);
        l_a = l_a * alpha_a + laa;
        l_b = l_b * alpha_b + lba;

        #pragma unroll
        for (int nt = 0; nt < 8; nt++) {
            o[nt][0] *= alpha_a; o[nt][1] *= alpha_a;
            o[nt][2] *= alpha_b; o[nt][3] *= alpha_b;
        }

        unsigned ph[4][4], pl[4][4];
        #pragma unroll
        for (int k2 = 0; k2 < 4; k2++) {
            int n0 = 2 * k2, n1 = 2 * k2 + 1;
            #pragma unroll
            for (int e = 0; e < 4; e++) {
                int nt = (e < 2) ? n0 : n1;
                int e0 = (e & 1) ? 2 : 0;
                float pa = p[nt][e0], pb = p[nt][e0 + 1];
                unsigned hp = pk_bf2(pa, pb);
                float ha = __uint_as_float(hp << 16);
                float hb = __uint_as_float(hp & 0xffff0000u);
                ph[k2][e] = hp;
                pl[k2][e] = pk_bf2(pa - ha, pb - hb);
            }
        }

        #pragma unroll
        for (int nt = 0; nt < 8; nt++) {
            unsigned vh[8], vl[8];
            uint32_t rowoff = (uint32_t)((nt * 8 + l7) * 144 + q4 * 16);
            ldsm_x4(vh,     vBh + rowoff);
            ldsm_x4(vh + 4, vBh + rowoff + 64);
            ldsm_x4(vl,     vBl + rowoff);
            ldsm_x4(vl + 4, vBl + rowoff + 64);
            #pragma unroll
            for (int k2 = 0; k2 < 4; k2++) {
                mma_bf16(o[nt], ph[k2], vh + k2 * 2);
                mma_bf16(o[nt], ph[k2], vl + k2 * 2);
                mma_bf16(o[nt], pl[k2], vh + k2 * 2);
            }
        }
    }

    size_t pa_off = ((size_t)kb * ROWS + bT + ra) * HS;
    size_t pb_off = ((size_t)kb * ROWS + bT + rb) * HS;
    #pragma unroll
    for (int nt = 0; nt < 8; nt++) {
        *(float2*)&g_po[pa_off + nt * 8 + 2 * tig] = make_float2(o[nt][0], o[nt][1]);
        *(float2*)&g_po[pb_off + nt * 8 + 2 * tig] = make_float2(o[nt][2], o[nt][3]);
    }
    if (tig == 0) {
        g_pm[kb * ROWS + bT + ra] = m_a * 8.0f;
        g_pl[kb * ROWS + bT + ra] = l_a;
        g_pm[kb * ROWS + bT + rb] = m_b * 8.0f;
        g_pl[kb * ROWS + bT + rb] = l_b;
    }
}

/* ---------------- combine split partials (high-ILP) ---------------------- */
__global__ __launch_bounds__(256)
void attn_combine_kernel(float* __restrict__ out) {
    int t = blockIdx.x * blockDim.x + threadIdx.x;
    if (t >= ROWS * 16) return;
    int row = t >> 4;
    int d4  = t & 15;
    int smax = (row & (TT - 1)) >> 8;      /* active splits: 0..smax, <= 7 */

    float mm[NS], ll[NS];
    #pragma unroll
    for (int s = 0; s < NS; s++) {
        bool a = (s <= smax);
        mm[s] = a ? g_pm[s * ROWS + row] : -CUDART_INF_F;
        ll[s] = a ? g_pl[s * ROWS + row] : 0.f;
    }
    float4 po[NS];
    #pragma unroll
    for (int s = 0; s < NS; s++) {
        po[s] = (s <= smax)
              ? ((const float4*)g_po)[((size_t)s * ROWS + row) * 16 + d4]
              : make_float4(0.f, 0.f, 0.f, 0.f);
    }

    float m = -CUDART_INF_F;
    #pragma unroll
    for (int s = 0; s < NS; s++) m = fmaxf(m, mm[s]);

    float l = 0.f;
    float4 acc = make_float4(0.f, 0.f, 0.f, 0.f);
    #pragma unroll
    for (int s = 0; s < NS; s++) {
        float wgt = __expf(mm[s] - m);     /* -inf -> 0 */
        l += ll[s] * wgt;
        acc.x = fmaf(wgt, po[s].x, acc.x);
        acc.y = fmaf(wgt, po[s].y, acc.y);
        acc.z = fmaf(wgt, po[s].z, acc.z);
        acc.w = fmaf(wgt, po[s].w, acc.w);
    }
    float inv = 1.f / l;
    ((float4*)out)[(size_t)row * 16 + d4] =
        make_float4(acc.x * inv, acc.y * inv, acc.z * inv, acc.w * inv);
}

/* ---------------- launch ------------------------------------------------ */
extern "C" void kernel_launch(void* const* d_in, const int* in_sizes, int n_in,
                              void* d_out, int out_size) {
    (void)in_sizes; (void)n_in; (void)out_size;
    const float* x  = (const float*)d_in[0];
    const float* Wq = (const float*)d_in[1];
    const float* bq = (const float*)d_in[2];
    const float* Wk = (const float*)d_in[3];
    const float* bk = (const float*)d_in[4];
    const float* Wv = (const float*)d_in[5];

    build_b_kernel<<<NCOL * DM / 256, 256>>>(Wq, Wk, Wv);
    qkv_mma_kernel<<<dim3(ROWS / 128, 3), 256>>>(x, bq, bk);
    attn_mma_kernel<<<dim3(TRI2, BB), 256>>>();
    attn_combine_kernel<<<(ROWS * 16 + 255) / 256, 256>>>((float*)d_out);
}